// round 8
// baseline (speedup 1.0000x reference)
#include <cuda_runtime.h>
#include <cuda_bf16.h>
#include <cstdint>

// Problem constants
#define B_      2
#define N_      100000
#define NPTS    (B_ * N_)          // 200000
#define RES     256
#define RES2    65536
#define NPIX    (B_ * RES * RES)   // 131072

// Output layout (concatenated, return order: out, before_pool, x_after, c)
#define OUT_OFF 0
#define BP_OFF  4194304            // 2*128*128*128
#define XA_OFF  20971520           // BP_OFF + 2*128*256*256
#define C_OFF   37748736           // XA_OFF + 2*128*256*256

#define MTILES  1563               // ceil(200000/128)

// ---------------- device scratch (no allocations allowed) ----------------
__device__ __align__(128) float g_xat[(size_t)NPIX * 128];     // x_after [b][y][x][c] fp32
__device__ __align__(128) float g_sums[(size_t)B_ * 128 * RES2];
__device__ __align__(128) float g_cnt[(size_t)B_ * RES2];
__device__ __align__(128) int   g_idx[NPTS];

// channel-last bf16 hi/lo activations
__device__ __align__(128) __nv_bfloat16 g_x1h[(size_t)NPIX * 64];   // x_xy
__device__ __align__(128) __nv_bfloat16 g_x1l[(size_t)NPIX * 64];
__device__ __align__(128) __nv_bfloat16 g_xah[(size_t)NPIX * 64];   // x_after_conv
__device__ __align__(128) __nv_bfloat16 g_xal[(size_t)NPIX * 64];
__device__ __align__(128) __nv_bfloat16 g_c1h[(size_t)NPIX * 128];  // relu(conv1)
__device__ __align__(128) __nv_bfloat16 g_c1l[(size_t)NPIX * 128];
__device__ __align__(128) __nv_bfloat16 g_c2h[(size_t)NPIX * 128];  // relu(conv2)
__device__ __align__(128) __nv_bfloat16 g_c2l[(size_t)NPIX * 128];

// point-pipeline bf16 hi/lo
__device__ __align__(128) __nv_bfloat16 g_c0h[(size_t)NPTS * 128];
__device__ __align__(128) __nv_bfloat16 g_c0l[(size_t)NPTS * 128];
__device__ __align__(128) __nv_bfloat16 g_th [(size_t)NPTS * 256];
__device__ __align__(128) __nv_bfloat16 g_tl [(size_t)NPTS * 256];
__device__ __align__(128) __nv_bfloat16 g_clh[(size_t)NPTS * 64];
__device__ __align__(128) __nv_bfloat16 g_cll[(size_t)NPTS * 64];

// packed weights bf16 hi/lo
__device__ __align__(128) __nv_bfloat16 g_w1t_h[256 * 128];   // fc1 [N][K]
__device__ __align__(128) __nv_bfloat16 g_w1t_l[256 * 128];
__device__ __align__(128) __nv_bfloat16 g_w2t_h[128 * 256];   // fc2 [N][K]
__device__ __align__(128) __nv_bfloat16 g_w2t_l[128 * 256];
__device__ __align__(128) __nv_bfloat16 g_wct_h[128 * 64];    // fcc [N][K]
__device__ __align__(128) __nv_bfloat16 g_wct_l[128 * 64];
__device__ __align__(128) __nv_bfloat16 g_wc1h[9 * 128 * 64];   // conv1 [tap][co][ci]
__device__ __align__(128) __nv_bfloat16 g_wc1l[9 * 128 * 64];
__device__ __align__(128) __nv_bfloat16 g_wc2h[9 * 128 * 128];  // conv2 [tap][co][ci]
__device__ __align__(128) __nv_bfloat16 g_wc2l[9 * 128 * 128];
__device__ __align__(128) __nv_bfloat16 g_wxh[128 * 64];        // conv1x1 [co][ci]
__device__ __align__(128) __nv_bfloat16 g_wxl[128 * 64];

// ---------------- helpers ----------------
__device__ __forceinline__ uint32_t smem_u32(const void* p) {
    uint32_t a;
    asm("{ .reg .u64 t; cvta.to.shared.u64 t, %1; cvt.u32.u64 %0, t; }" : "=r"(a) : "l"(p));
    return a;
}
#define SW128(o) ((o) ^ (((o) >> 3) & 0x70))

__device__ __forceinline__ void ldm_x4(uint32_t* r, uint32_t addr) {
    asm volatile("ldmatrix.sync.aligned.m8n8.x4.shared.b16 {%0,%1,%2,%3}, [%4];"
        : "=r"(r[0]), "=r"(r[1]), "=r"(r[2]), "=r"(r[3]) : "r"(addr));
}
__device__ __forceinline__ void mma16816(float* c, const uint32_t* a, const uint32_t* b) {
    asm volatile("mma.sync.aligned.m16n8k16.row.col.f32.bf16.bf16.f32 "
        "{%0,%1,%2,%3}, {%4,%5,%6,%7}, {%8,%9}, {%0,%1,%2,%3};"
        : "+f"(c[0]), "+f"(c[1]), "+f"(c[2]), "+f"(c[3])
        : "r"(a[0]), "r"(a[1]), "r"(a[2]), "r"(a[3]), "r"(b[0]), "r"(b[1]));
}

__device__ __forceinline__ void split2(float a, float b, uint32_t& uh, uint32_t& ul) {
    __nv_bfloat16 ha = __float2bfloat16(a), hb = __float2bfloat16(b);
    float ra = a - __bfloat162float(ha), rb = b - __bfloat162float(hb);
    __nv_bfloat16 la = __float2bfloat16(ra), lb = __float2bfloat16(rb);
    uh = ((uint32_t)__bfloat16_as_ushort(hb) << 16) | __bfloat16_as_ushort(ha);
    ul = ((uint32_t)__bfloat16_as_ushort(lb) << 16) | __bfloat16_as_ushort(la);
}
__device__ __forceinline__ float bf2f_lo(uint32_t u) {
    return __bfloat162float(__ushort_as_bfloat16((unsigned short)(u & 0xFFFF)));
}
__device__ __forceinline__ float bf2f_hi(uint32_t u) {
    return __bfloat162float(__ushort_as_bfloat16((unsigned short)(u >> 16)));
}

// shared warp-level compute on staged [rows][64] SW128 tiles
__device__ __forceinline__ void mma_block_pass(uint32_t smAb, uint32_t smBb, int rowoff,
                                               int warp_m, int warp_n, int lane,
                                               float acc[2][8][4])
{
    #pragma unroll
    for (int ks = 0; ks < 4; ks++) {
        int kc = ks * 2;
        uint32_t a[2][4];
        #pragma unroll
        for (int i = 0; i < 2; i++) {
            int r = warp_m * 32 + i * 16 + (lane & 15) + rowoff;
            int c = kc + (lane >> 4);
            ldm_x4(a[i], smAb + SW128((uint32_t)(r * 128 + c * 16)));
        }
        uint32_t b[8][2];
        #pragma unroll
        for (int j2 = 0; j2 < 4; j2++) {
            int r = warp_n * 64 + j2 * 16 + (lane & 15);
            int c = kc + (lane >> 4);
            uint32_t t[4];
            ldm_x4(t, smBb + SW128((uint32_t)(r * 128 + c * 16)));
            b[j2 * 2][0] = t[0]; b[j2 * 2 + 1][0] = t[1];
            b[j2 * 2][1] = t[2]; b[j2 * 2 + 1][1] = t[3];
        }
        #pragma unroll
        for (int i = 0; i < 2; i++)
            #pragma unroll
            for (int j = 0; j < 8; j++)
                mma16816(acc[i][j], a[i], b[j]);
    }
}

// ---------------- zero scratch accumulators ----------------
__global__ void zero_kernel() {
    const size_t ns = (size_t)B_ * 128 * RES2;
    const size_t total = ns + (size_t)B_ * RES2;
    for (size_t i = (size_t)blockIdx.x * blockDim.x + threadIdx.x; i < total;
         i += (size_t)gridDim.x * blockDim.x) {
        if (i < ns) g_sums[i] = 0.f;
        else        g_cnt[i - ns] = 0.f;
    }
}

// ---------------- input NCHW fp32 -> channel-last bf16 hi/lo ----------------
__global__ void cvt_kernel(const float* __restrict__ src, int sel)
{
    __shared__ float s[64 * 65];
    uint32_t* dh = sel ? (uint32_t*)g_xah : (uint32_t*)g_x1h;
    uint32_t* dl = sel ? (uint32_t*)g_xal : (uint32_t*)g_x1l;
    int tid = threadIdx.x;
    int x0 = blockIdx.x * 64, y = blockIdx.y, b = blockIdx.z;
    #pragma unroll
    for (int i = 0; i < 16; i++) {
        int lin = tid + i * 256;
        int x = lin & 63, ci = lin >> 6;
        s[x * 65 + ci] = src[(((size_t)b * 64 + ci) * 256 + y) * 256 + x0 + x];
    }
    __syncthreads();
    #pragma unroll
    for (int i = 0; i < 8; i++) {
        int lin = tid + i * 256;
        int c2 = lin & 31, x = lin >> 5;
        float a = s[x * 65 + c2 * 2], bb = s[x * 65 + c2 * 2 + 1];
        uint32_t uh, ul; split2(a, bb, uh, ul);
        size_t o = (((size_t)b * 256 + y) * 256 + x0 + x) * 32 + c2;
        dh[o] = uh; dl[o] = ul;
    }
}

// ---------------- c_last -> bf16 hi/lo ----------------
__global__ void clconv_kernel(const float* __restrict__ clast)
{
    int i = blockIdx.x * blockDim.x + threadIdx.x;
    if (i >= NPTS * 32) return;
    float a = clast[2 * i], b = clast[2 * i + 1];
    uint32_t uh, ul;
    split2(a, b, uh, ul);
    ((uint32_t*)g_clh)[i] = uh;
    ((uint32_t*)g_cll)[i] = ul;
}

// ---------------- weight packing ----------------
__global__ void wconv_kernel(const float* __restrict__ W1, const float* __restrict__ W2,
                             const float* __restrict__ Wc, const float* __restrict__ WC1,
                             const float* __restrict__ WC2, const float* __restrict__ WX)
{
    int i = blockIdx.x * blockDim.x + threadIdx.x;
    if (i < 256 * 128) {            // fc1: [K=128][N=256] -> [N][K]
        int n = i >> 7, k = i & 127;
        float v = W1[k * 256 + n];
        __nv_bfloat16 h = __float2bfloat16(v);
        g_w1t_h[i] = h; g_w1t_l[i] = __float2bfloat16(v - __bfloat162float(h));
    }
    if (i < 128 * 256) {            // fc2
        int n = i >> 8, k = i & 255;
        float v = W2[k * 128 + n];
        __nv_bfloat16 h = __float2bfloat16(v);
        g_w2t_h[i] = h; g_w2t_l[i] = __float2bfloat16(v - __bfloat162float(h));
    }
    if (i < 128 * 64) {             // fcc
        int n = i >> 6, k = i & 63;
        float v = Wc[k * 128 + n];
        __nv_bfloat16 h = __float2bfloat16(v);
        g_wct_h[i] = h; g_wct_l[i] = __float2bfloat16(v - __bfloat162float(h));
    }
    if (i < 9 * 128 * 64) {         // conv1 OIHW -> [tap][co][ci]
        int t = i / 8192; int r = i - t * 8192; int co = r >> 6, ci = r & 63;
        float v = WC1[((size_t)(co * 64 + ci)) * 9 + t];
        __nv_bfloat16 h = __float2bfloat16(v);
        g_wc1h[i] = h; g_wc1l[i] = __float2bfloat16(v - __bfloat162float(h));
    }
    if (i < 9 * 128 * 128) {        // conv2 OIHW -> [tap][co][ci]
        int t = i / 16384; int r = i & 16383; int co = r >> 7, ci = r & 127;
        float v = WC2[((size_t)(co * 128 + ci)) * 9 + t];
        __nv_bfloat16 h = __float2bfloat16(v);
        g_wc2h[i] = h; g_wc2l[i] = __float2bfloat16(v - __bfloat162float(h));
    }
    if (i < 128 * 64) {             // conv1x1 [co][ci]
        float v = WX[i];
        __nv_bfloat16 h = __float2bfloat16(v);
        g_wxh[i] = h; g_wxl[i] = __float2bfloat16(v - __bfloat162float(h));
    }
}

// ---------------- conv staging ----------------
__device__ __forceinline__ void conv_stageA(char* smAp, const __nv_bfloat16* rowsrc,
                                            int x0, int rowok, int ldci, int tid)
{
    __syncthreads();
    for (int e = tid; e < 1040; e += 256) {
        int r = e >> 3, q = e & 7;
        int gx = x0 - 1 + r;
        uint4 v = make_uint4(0, 0, 0, 0);
        if (rowok && (unsigned)gx < 256u)
            v = *(const uint4*)(rowsrc + (size_t)gx * ldci + q * 8);
        *(uint4*)(smAp + SW128(r * 128 + q * 16)) = v;
    }
    __syncthreads();
}
__device__ __forceinline__ void conv_stageB(char* smBp, const __nv_bfloat16* wsrc,
                                            int ldw, int tid)
{
    __syncthreads();
    for (int e = tid; e < 1024; e += 256) {
        int r = e >> 3, q = e & 7;
        uint4 v = *(const uint4*)(wsrc + (size_t)r * ldw + q * 8);
        *(uint4*)(smBp + SW128(r * 128 + q * 16)) = v;
    }
    __syncthreads();
}

// ---------------- implicit-GEMM 3x3 conv via HMMA, 3-term bf16 split ----------------
// Block: 128 x-pixels (one row y) x 128 couts; 8 warps (4M x 2N).
template<int CIN, int LAYER>
__global__ __launch_bounds__(256)
void conv_hmma_kernel(const float* __restrict__ bias)
{
    __shared__ __align__(128) __nv_bfloat16 smA[130 * 64];
    __shared__ __align__(128) __nv_bfloat16 smB[128 * 64];
    char* smAp = (char*)smA; char* smBp = (char*)smB;
    uint32_t smAb = smem_u32(smA), smBb = smem_u32(smB);

    const __nv_bfloat16* inh = (LAYER == 1) ? g_x1h : g_c1h;
    const __nv_bfloat16* inl = (LAYER == 1) ? g_x1l : g_c1l;
    const __nv_bfloat16* wh  = (LAYER == 1) ? g_wc1h : g_wc2h;
    const __nv_bfloat16* wl  = (LAYER == 1) ? g_wc1l : g_wc2l;
    uint32_t* outh = (uint32_t*)((LAYER == 1) ? g_c1h : g_c2h);
    uint32_t* outl = (uint32_t*)((LAYER == 1) ? g_c1l : g_c2l);

    const int tid = threadIdx.x, lane = tid & 31, wid = tid >> 5;
    const int warp_m = wid & 3, warp_n = wid >> 2;
    const int x0 = blockIdx.x * 128;
    const int y = blockIdx.y;
    const int b = blockIdx.z;

    float acc[2][8][4] = {};

    for (int cc = 0; cc < CIN / 64; cc++) {
        for (int ky = 0; ky < 3; ky++) {
            int gy = y + ky - 1;
            int rowok = ((unsigned)gy < 256u) ? 1 : 0;
            size_t rb = (((size_t)b * 256 + (rowok ? gy : 0)) * 256) * CIN + cc * 64;
            // term hh and hl share A_h
            conv_stageA(smAp, inh + rb, x0, rowok, CIN, tid);
            for (int kx = 0; kx < 3; kx++) {
                conv_stageB(smBp, wh + ((size_t)(ky * 3 + kx) * 128) * CIN + cc * 64, CIN, tid);
                mma_block_pass(smAb, smBb, kx, warp_m, warp_n, lane, acc);
            }
            for (int kx = 0; kx < 3; kx++) {
                conv_stageB(smBp, wl + ((size_t)(ky * 3 + kx) * 128) * CIN + cc * 64, CIN, tid);
                mma_block_pass(smAb, smBb, kx, warp_m, warp_n, lane, acc);
            }
            // term lh
            conv_stageA(smAp, inl + rb, x0, rowok, CIN, tid);
            for (int kx = 0; kx < 3; kx++) {
                conv_stageB(smBp, wh + ((size_t)(ky * 3 + kx) * 128) * CIN + cc * 64, CIN, tid);
                mma_block_pass(smAb, smBb, kx, warp_m, warp_n, lane, acc);
            }
        }
    }

    // epilogue: bias + relu -> split hi/lo -> channel-last [pixel][128]
    const int g = lane >> 2, t4 = lane & 3;
    size_t pixbase = ((size_t)b * 256 + y) * 256 + x0;
    #pragma unroll
    for (int i = 0; i < 2; i++) {
        size_t pA = pixbase + warp_m * 32 + i * 16 + g;
        size_t pB = pA + 8;
        #pragma unroll
        for (int j = 0; j < 8; j++) {
            int col = warp_n * 64 + j * 8 + t4 * 2;
            float b0 = bias[col], b1v = bias[col + 1];
            uint32_t uh, ul;
            float v0 = fmaxf(acc[i][j][0] + b0, 0.f);
            float v1 = fmaxf(acc[i][j][1] + b1v, 0.f);
            split2(v0, v1, uh, ul);
            outh[pA * 64 + (col >> 1)] = uh;
            outl[pA * 64 + (col >> 1)] = ul;
            float v2 = fmaxf(acc[i][j][2] + b0, 0.f);
            float v3 = fmaxf(acc[i][j][3] + b1v, 0.f);
            split2(v2, v3, uh, ul);
            outh[pB * 64 + (col >> 1)] = uh;
            outl[pB * 64 + (col >> 1)] = ul;
        }
    }
}

// ---------------- fc-style GEMM staging chunk (validated R6 core) ----------------
__device__ __forceinline__ void gemm_chunk(
    char* smAp, char* smBp, uint32_t smAb, uint32_t smBb,
    const __nv_bfloat16* __restrict__ Ag, int lda, int m0,
    const __nv_bfloat16* __restrict__ Bg, int ldb, int n0, int koff,
    int tid, int warp_m, int warp_n, int lane,
    float acc[2][8][4])
{
    __syncthreads();
    for (int e = tid; e < 1024; e += 256) {
        int row = e >> 3, uc = e & 7;
        int grow = m0 + row;
        uint4 v = make_uint4(0, 0, 0, 0);
        if (grow < NPTS)
            v = *(const uint4*)(Ag + (size_t)grow * lda + koff + uc * 8);
        *(uint4*)(smAp + SW128(row * 128 + uc * 16)) = v;
    }
    for (int e = tid; e < 1024; e += 256) {
        int row = e >> 3, uc = e & 7;
        uint4 v = *(const uint4*)(Bg + (size_t)(n0 + row) * ldb + koff + uc * 8);
        *(uint4*)(smBp + SW128(row * 128 + uc * 16)) = v;
    }
    __syncthreads();
    mma_block_pass(smAb, smBb, 0, warp_m, warp_n, lane, acc);
}

// ---------------- fuse1x1: acc = x_ac @ Wx (3-term); out = relu_conv2 + acc + b1x1 ----------------
__global__ __launch_bounds__(256)
void fuse1x1_kernel(const float* __restrict__ bx)
{
    __shared__ __align__(128) __nv_bfloat16 smA[128 * 64];
    __shared__ __align__(128) __nv_bfloat16 smB[128 * 64];
    char* smAp = (char*)smA; char* smBp = (char*)smB;
    uint32_t smAb = smem_u32(smA), smBb = smem_u32(smB);

    const int tid = threadIdx.x, lane = tid & 31, wid = tid >> 5;
    const int warp_m = wid & 3, warp_n = wid >> 2;
    const int m0 = blockIdx.x * 128;

    float acc[2][8][4] = {};
    const __nv_bfloat16* Aph[3] = {g_xah, g_xal, g_xah};
    const __nv_bfloat16* Bph[3] = {g_wxh, g_wxh, g_wxl};
    for (int ph = 0; ph < 3; ph++)
        gemm_chunk(smAp, smBp, smAb, smBb, Aph[ph], 64, m0,
                   Bph[ph], 64, 0, 0, tid, warp_m, warp_n, lane, acc);

    const uint32_t* c2h = (const uint32_t*)g_c2h;
    const uint32_t* c2l = (const uint32_t*)g_c2l;
    const int g = lane >> 2, t4 = lane & 3;
    #pragma unroll
    for (int i = 0; i < 2; i++) {
        size_t pA = (size_t)m0 + warp_m * 32 + i * 16 + g;
        size_t pB = pA + 8;
        #pragma unroll
        for (int j = 0; j < 8; j++) {
            int col = warp_n * 64 + j * 8 + t4 * 2;
            float bb0 = bx[col], bb1 = bx[col + 1];
            uint32_t ph = c2h[pA * 64 + (col >> 1)], pl = c2l[pA * 64 + (col >> 1)];
            float f0 = bf2f_lo(ph) + bf2f_lo(pl);
            float f1 = bf2f_hi(ph) + bf2f_hi(pl);
            *(float2*)&g_xat[pA * 128 + col] =
                make_float2(acc[i][j][0] + bb0 + f0, acc[i][j][1] + bb1 + f1);
            uint32_t qh = c2h[pB * 64 + (col >> 1)], ql = c2l[pB * 64 + (col >> 1)];
            float f2 = bf2f_lo(qh) + bf2f_lo(ql);
            float f3 = bf2f_hi(qh) + bf2f_hi(ql);
            *(float2*)&g_xat[pB * 128 + col] =
                make_float2(acc[i][j][2] + bb0 + f2, acc[i][j][3] + bb1 + f3);
        }
    }
}

// ---------------- g_xat [b][y][x][c] -> x_after NCHW fp32 ----------------
__global__ void xat2nchw_kernel(float* __restrict__ dst)
{
    __shared__ float s[32 * 33];
    int tid = threadIdx.x;
    int x0 = blockIdx.x * 32, y = blockIdx.y;
    int b = blockIdx.z >> 2, c0 = (blockIdx.z & 3) * 32;
    #pragma unroll
    for (int i = 0; i < 4; i++) {
        int lin = tid + i * 256;
        int c = lin & 31, x = lin >> 5;
        s[x * 33 + c] = g_xat[(((size_t)b * 256 + y) * 256 + x0 + x) * 128 + c0 + c];
    }
    __syncthreads();
    #pragma unroll
    for (int i = 0; i < 4; i++) {
        int lin = tid + i * 256;
        int x = lin & 31, c = lin >> 5;
        dst[(((size_t)b * 128 + c0 + c) * 256 + y) * 256 + x0 + x] = s[x * 33 + c];
    }
}

// ---------------- bilinear sampling (reads g_xat fp32) ----------------
__global__ void sample_kernel(const float* __restrict__ p)
{
    int gid  = blockIdx.x * blockDim.x + threadIdx.x;
    int wid  = gid >> 5;
    int lane = gid & 31;
    if (wid >= NPTS) return;
    int b = (wid >= N_) ? 1 : 0;

    float sx = p[(size_t)wid * 3 + 0];
    float sy = p[(size_t)wid * 3 + 1];
    float px = fminf(fmaxf(sx * 255.f, 0.f), 255.f);
    float py = fminf(fmaxf(sy * 255.f, 0.f), 255.f);
    float x0f = floorf(px), y0f = floorf(py);
    int x0 = (int)x0f, y0 = (int)y0f;
    int x1 = min(x0 + 1, 255), y1 = min(y0 + 1, 255);
    float wx = px - x0f, wy = py - y0f;
    float w00 = (1.f - wx) * (1.f - wy);
    float w01 = wx * (1.f - wy);
    float w10 = (1.f - wx) * wy;
    float w11 = wx * wy;

    const float4* F = (const float4*)g_xat;
    size_t r00 = ((size_t)(b * 256 + y0) * 256 + x0) * 32 + lane;
    size_t r01 = ((size_t)(b * 256 + y0) * 256 + x1) * 32 + lane;
    size_t r10 = ((size_t)(b * 256 + y1) * 256 + x0) * 32 + lane;
    size_t r11 = ((size_t)(b * 256 + y1) * 256 + x1) * 32 + lane;
    float4 f00 = F[r00], f01 = F[r01], f10 = F[r10], f11 = F[r11];
    float4 r;
    r.x = f00.x * w00 + f01.x * w01 + f10.x * w10 + f11.x * w11;
    r.y = f00.y * w00 + f01.y * w01 + f10.y * w10 + f11.y * w11;
    r.z = f00.z * w00 + f01.z * w01 + f10.z * w10 + f11.z * w11;
    r.w = f00.w * w00 + f01.w * w01 + f10.w * w10 + f11.w * w11;

    uint32_t h0, l0, h1, l1;
    split2(r.x, r.y, h0, l0);
    split2(r.z, r.w, h1, l1);
    uint32_t* ch = (uint32_t*)g_c0h;
    uint32_t* cl = (uint32_t*)g_c0l;
    size_t base = (size_t)wid * 64 + lane * 2;
    ch[base] = h0; ch[base + 1] = h1;
    cl[base] = l0; cl[base + 1] = l1;

    if (lane == 0) {
        int ix = min(max((int)(sx * 256.f), 0), 255);
        int iy = min(max((int)(sy * 256.f), 0), 255);
        int idx = ix + (iy << 8);
        g_idx[wid] = idx;
        atomicAdd(&g_cnt[b * RES2 + idx], 1.f);
    }
}

// ---------------- fc1: t = relu(c0 @ W1 + b1), 3-term bf16 split ----------------
__global__ __launch_bounds__(256)
void fc1_hmma_kernel(const float* __restrict__ bias)
{
    __shared__ __align__(128) __nv_bfloat16 smA[128 * 64];
    __shared__ __align__(128) __nv_bfloat16 smB[128 * 64];
    char* smAp = (char*)smA; char* smBp = (char*)smB;
    uint32_t smAb = smem_u32(smA), smBb = smem_u32(smB);

    const int tid = threadIdx.x, lane = tid & 31, wid = tid >> 5;
    const int warp_m = wid & 3, warp_n = wid >> 2;
    const int m0 = blockIdx.x * 128, n0 = blockIdx.y * 128;

    float acc[2][8][4] = {};
    const __nv_bfloat16* Aph[3] = {g_c0h, g_c0l, g_c0h};
    const __nv_bfloat16* Bph[3] = {g_w1t_h, g_w1t_h, g_w1t_l};
    for (int ph = 0; ph < 3; ph++)
        for (int kc = 0; kc < 2; kc++)
            gemm_chunk(smAp, smBp, smAb, smBb, Aph[ph], 128, m0,
                       Bph[ph], 128, n0, kc * 64, tid, warp_m, warp_n, lane, acc);

    uint32_t* th = (uint32_t*)g_th;
    uint32_t* tl = (uint32_t*)g_tl;
    const int g = lane >> 2, t4 = lane & 3;
    #pragma unroll
    for (int i = 0; i < 2; i++) {
        int rowA = m0 + warp_m * 32 + i * 16 + g;
        int rowB = rowA + 8;
        #pragma unroll
        for (int j = 0; j < 8; j++) {
            int col = n0 + warp_n * 64 + j * 8 + t4 * 2;
            float b0 = bias[col], b1 = bias[col + 1];
            if (rowA < NPTS) {
                float v0 = fmaxf(acc[i][j][0] + b0, 0.f);
                float v1 = fmaxf(acc[i][j][1] + b1, 0.f);
                uint32_t uh, ul; split2(v0, v1, uh, ul);
                size_t o = (size_t)rowA * 128 + (col >> 1);
                th[o] = uh; tl[o] = ul;
            }
            if (rowB < NPTS) {
                float v2 = fmaxf(acc[i][j][2] + b0, 0.f);
                float v3 = fmaxf(acc[i][j][3] + b1, 0.f);
                uint32_t uh, ul; split2(v2, v3, uh, ul);
                size_t o = (size_t)rowB * 128 + (col >> 1);
                th[o] = uh; tl[o] = ul;
            }
        }
    }
}

// ---------------- fc2: c = t@W2 + b2 + c_last@Wc + bc; write c; scatter-add ----------------
__global__ __launch_bounds__(256)
void fc2_hmma_kernel(const float* __restrict__ b2, const float* __restrict__ bc,
                     float* __restrict__ outc)
{
    __shared__ __align__(128) __nv_bfloat16 smA[128 * 64];
    __shared__ __align__(128) __nv_bfloat16 smB[128 * 64];
    char* smAp = (char*)smA; char* smBp = (char*)smB;
    uint32_t smAb = smem_u32(smA), smBb = smem_u32(smB);

    const int tid = threadIdx.x, lane = tid & 31, wid = tid >> 5;
    const int warp_m = wid & 3, warp_n = wid >> 2;
    const int m0 = blockIdx.x * 128;

    float acc[2][8][4] = {};
    const __nv_bfloat16* Aph[6] = {g_th, g_tl, g_th, g_clh, g_cll, g_clh};
    const __nv_bfloat16* Bph[6] = {g_w2t_h, g_w2t_h, g_w2t_l, g_wct_h, g_wct_h, g_wct_l};
    const int ldp[6] = {256, 256, 256, 64, 64, 64};
    const int ncp[6] = {4, 4, 4, 1, 1, 1};
    for (int ph = 0; ph < 6; ph++)
        for (int kc = 0; kc < ncp[ph]; kc++)
            gemm_chunk(smAp, smBp, smAb, smBb, Aph[ph], ldp[ph], m0,
                       Bph[ph], ldp[ph], 0, kc * 64, tid, warp_m, warp_n, lane, acc);

    const int g = lane >> 2, t4 = lane & 3;
    int rows[4], idxs[4], bbs[4];
    #pragma unroll
    for (int i = 0; i < 2; i++) {
        rows[i * 2]     = m0 + warp_m * 32 + i * 16 + g;
        rows[i * 2 + 1] = rows[i * 2] + 8;
    }
    #pragma unroll
    for (int k = 0; k < 4; k++) {
        idxs[k] = 0; bbs[k] = 0;
        if (rows[k] < NPTS) { idxs[k] = g_idx[rows[k]]; bbs[k] = (rows[k] >= N_) ? 1 : 0; }
    }
    #pragma unroll
    for (int i = 0; i < 2; i++) {
        #pragma unroll
        for (int j = 0; j < 8; j++) {
            int col = warp_n * 64 + j * 8 + t4 * 2;
            float bb0 = b2[col] + bc[col], bb1 = b2[col + 1] + bc[col + 1];
            int rA = rows[i * 2], rB = rows[i * 2 + 1];
            float v0 = acc[i][j][0] + bb0, v1 = acc[i][j][1] + bb1;
            float v2 = acc[i][j][2] + bb0, v3 = acc[i][j][3] + bb1;
            if (rA < NPTS) {
                *(float2*)(outc + (size_t)rA * 128 + col) = make_float2(v0, v1);
                int ia = idxs[i * 2], ba = bbs[i * 2];
                atomicAdd(&g_sums[((size_t)(ba * 128 + col)) * RES2 + ia], v0);
                atomicAdd(&g_sums[((size_t)(ba * 128 + col + 1)) * RES2 + ia], v1);
            }
            if (rB < NPTS) {
                *(float2*)(outc + (size_t)rB * 128 + col) = make_float2(v2, v3);
                int ib = idxs[i * 2 + 1], bbx = bbs[i * 2 + 1];
                atomicAdd(&g_sums[((size_t)(bbx * 128 + col)) * RES2 + ib], v2);
                atomicAdd(&g_sums[((size_t)(bbx * 128 + col + 1)) * RES2 + ib], v3);
            }
        }
    }
}

// ---------------- plane finalize + maxpool ----------------
__global__ void plane_kernel(float* __restrict__ dout)
{
    int i = blockIdx.x * blockDim.x + threadIdx.x;
    if (i >= B_ * 128 * RES2) return;
    int b = i >> 23;
    int idx = i & 65535;
    float cnt = g_cnt[(b << 16) + idx];
    dout[BP_OFF + i] = g_sums[i] / fmaxf(cnt, 1.f);
}

__global__ void pool_kernel(float* __restrict__ dout)
{
    int i = blockIdx.x * blockDim.x + threadIdx.x;
    if (i >= B_ * 128 * 128 * 128) return;
    int px = i & 127, py = (i >> 7) & 127, bc = i >> 14;
    const float* pl = dout + BP_OFF + (size_t)bc * RES2;
    int r0 = (py * 2) * 256 + px * 2;
    float v = fmaxf(fmaxf(pl[r0], pl[r0 + 1]), fmaxf(pl[r0 + 256], pl[r0 + 257]));
    dout[OUT_OFF + i] = v;
}

// ---------------- launch ----------------
extern "C" void kernel_launch(void* const* d_in, const int* in_sizes, int n_in,
                              void* d_out, int out_size)
{
    const float* p     = (const float*)d_in[0];
    const float* x_xy  = (const float*)d_in[1];
    const float* x_ac  = (const float*)d_in[2];
    const float* clast = (const float*)d_in[3];
    const float* w1    = (const float*)d_in[4];
    const float* bb1   = (const float*)d_in[5];
    const float* w2    = (const float*)d_in[6];
    const float* bb2   = (const float*)d_in[7];
    const float* w1x1  = (const float*)d_in[8];
    const float* b1x1  = (const float*)d_in[9];
    const float* wfc1  = (const float*)d_in[10];
    const float* bfc1  = (const float*)d_in[11];
    const float* wfc2  = (const float*)d_in[12];
    const float* bfc2  = (const float*)d_in[13];
    const float* wfcc  = (const float*)d_in[14];
    const float* bfcc  = (const float*)d_in[15];
    float* out = (float*)d_out;

    zero_kernel<<<2048, 256>>>();
    wconv_kernel<<<576, 256>>>(wfc1, wfc2, wfcc, w1, w2, w1x1);
    clconv_kernel<<<(NPTS * 32 + 255) / 256, 256>>>(clast);
    cvt_kernel<<<dim3(4, 256, 2), 256>>>(x_xy, 0);
    cvt_kernel<<<dim3(4, 256, 2), 256>>>(x_ac, 1);
    conv_hmma_kernel<64, 1><<<dim3(2, 256, 2), 256>>>(bb1);
    conv_hmma_kernel<128, 2><<<dim3(2, 256, 2), 256>>>(bb2);
    fuse1x1_kernel<<<NPIX / 128, 256>>>(b1x1);
    xat2nchw_kernel<<<dim3(8, 256, 8), 256>>>(out + XA_OFF);
    sample_kernel<<<(NPTS * 32 + 255) / 256, 256>>>(p);
    fc1_hmma_kernel<<<dim3(MTILES, 2), 256>>>(bfc1);
    fc2_hmma_kernel<<<dim3(MTILES, 1), 256>>>(bfc2, bfcc, out + C_OFF);
    plane_kernel<<<(B_ * 128 * RES2) / 256, 256>>>(out);
    pool_kernel<<<(B_ * 128 * 128 * 128) / 256, 256>>>(out);
}

// round 9
// speedup vs baseline: 1.0117x; 1.0117x over previous
#include <cuda_runtime.h>
#include <cuda_bf16.h>
#include <cstdint>

// Problem constants
#define B_      2
#define N_      100000
#define NPTS    (B_ * N_)          // 200000
#define RES     256
#define RES2    65536
#define NPIX    (B_ * RES * RES)   // 131072

// Output layout (concatenated, return order: out, before_pool, x_after, c)
#define OUT_OFF 0
#define BP_OFF  4194304            // 2*128*128*128
#define XA_OFF  20971520           // BP_OFF + 2*128*256*256
#define C_OFF   37748736           // XA_OFF + 2*128*256*256

#define MTILES  1563               // ceil(200000/128)

// ---------------- device scratch (no allocations allowed) ----------------
__device__ __align__(128) float g_xat[(size_t)NPIX * 128];     // x_after [b][y][x][c] fp32
__device__ __align__(128) float g_sums[(size_t)B_ * 128 * RES2];
__device__ __align__(128) float g_cnt[(size_t)B_ * RES2];
__device__ __align__(128) int   g_idx[NPTS];

// channel-last bf16 hi/lo activations
__device__ __align__(128) __nv_bfloat16 g_x1h[(size_t)NPIX * 64];   // x_xy
__device__ __align__(128) __nv_bfloat16 g_x1l[(size_t)NPIX * 64];
__device__ __align__(128) __nv_bfloat16 g_xah[(size_t)NPIX * 64];   // x_after_conv
__device__ __align__(128) __nv_bfloat16 g_xal[(size_t)NPIX * 64];
__device__ __align__(128) __nv_bfloat16 g_c1h[(size_t)NPIX * 128];  // relu(conv1)
__device__ __align__(128) __nv_bfloat16 g_c1l[(size_t)NPIX * 128];
__device__ __align__(128) __nv_bfloat16 g_c2h[(size_t)NPIX * 128];  // relu(conv2)
__device__ __align__(128) __nv_bfloat16 g_c2l[(size_t)NPIX * 128];

// point-pipeline bf16 hi/lo
__device__ __align__(128) __nv_bfloat16 g_c0h[(size_t)NPTS * 128];
__device__ __align__(128) __nv_bfloat16 g_c0l[(size_t)NPTS * 128];
__device__ __align__(128) __nv_bfloat16 g_th [(size_t)NPTS * 256];
__device__ __align__(128) __nv_bfloat16 g_tl [(size_t)NPTS * 256];
__device__ __align__(128) __nv_bfloat16 g_clh[(size_t)NPTS * 64];
__device__ __align__(128) __nv_bfloat16 g_cll[(size_t)NPTS * 64];

// packed weights bf16 hi/lo
__device__ __align__(128) __nv_bfloat16 g_w1t_h[256 * 128];   // fc1 [N][K]
__device__ __align__(128) __nv_bfloat16 g_w1t_l[256 * 128];
__device__ __align__(128) __nv_bfloat16 g_w2t_h[128 * 256];   // fc2 [N][K]
__device__ __align__(128) __nv_bfloat16 g_w2t_l[128 * 256];
__device__ __align__(128) __nv_bfloat16 g_wct_h[128 * 64];    // fcc [N][K]
__device__ __align__(128) __nv_bfloat16 g_wct_l[128 * 64];
__device__ __align__(128) __nv_bfloat16 g_wc1h[9 * 128 * 64];   // conv1 [tap][co][ci]
__device__ __align__(128) __nv_bfloat16 g_wc1l[9 * 128 * 64];
__device__ __align__(128) __nv_bfloat16 g_wc2h[9 * 128 * 128];  // conv2 [tap][co][ci]
__device__ __align__(128) __nv_bfloat16 g_wc2l[9 * 128 * 128];
__device__ __align__(128) __nv_bfloat16 g_wxh[128 * 64];        // conv1x1 [co][ci]
__device__ __align__(128) __nv_bfloat16 g_wxl[128 * 64];

// ---------------- helpers ----------------
__device__ __forceinline__ uint32_t smem_u32(const void* p) {
    uint32_t a;
    asm("{ .reg .u64 t; cvta.to.shared.u64 t, %1; cvt.u32.u64 %0, t; }" : "=r"(a) : "l"(p));
    return a;
}
#define SW128(o) ((o) ^ (((o) >> 3) & 0x70))

__device__ __forceinline__ void ldm_x4(uint32_t* r, uint32_t addr) {
    asm volatile("ldmatrix.sync.aligned.m8n8.x4.shared.b16 {%0,%1,%2,%3}, [%4];"
        : "=r"(r[0]), "=r"(r[1]), "=r"(r[2]), "=r"(r[3]) : "r"(addr));
}
__device__ __forceinline__ void mma16816(float* c, const uint32_t* a, const uint32_t* b) {
    asm volatile("mma.sync.aligned.m16n8k16.row.col.f32.bf16.bf16.f32 "
        "{%0,%1,%2,%3}, {%4,%5,%6,%7}, {%8,%9}, {%0,%1,%2,%3};"
        : "+f"(c[0]), "+f"(c[1]), "+f"(c[2]), "+f"(c[3])
        : "r"(a[0]), "r"(a[1]), "r"(a[2]), "r"(a[3]), "r"(b[0]), "r"(b[1]));
}

__device__ __forceinline__ void split2(float a, float b, uint32_t& uh, uint32_t& ul) {
    __nv_bfloat16 ha = __float2bfloat16(a), hb = __float2bfloat16(b);
    float ra = a - __bfloat162float(ha), rb = b - __bfloat162float(hb);
    __nv_bfloat16 la = __float2bfloat16(ra), lb = __float2bfloat16(rb);
    uh = ((uint32_t)__bfloat16_as_ushort(hb) << 16) | __bfloat16_as_ushort(ha);
    ul = ((uint32_t)__bfloat16_as_ushort(lb) << 16) | __bfloat16_as_ushort(la);
}
__device__ __forceinline__ float bf2f_lo(uint32_t u) {
    return __bfloat162float(__ushort_as_bfloat16((unsigned short)(u & 0xFFFF)));
}
__device__ __forceinline__ float bf2f_hi(uint32_t u) {
    return __bfloat162float(__ushort_as_bfloat16((unsigned short)(u >> 16)));
}

// shared warp-level compute on staged [rows][64] SW128 tiles
__device__ __forceinline__ void mma_block_pass(uint32_t smAb, uint32_t smBb, int rowoff,
                                               int warp_m, int warp_n, int lane,
                                               float acc[2][8][4])
{
    #pragma unroll
    for (int ks = 0; ks < 4; ks++) {
        int kc = ks * 2;
        uint32_t a[2][4];
        #pragma unroll
        for (int i = 0; i < 2; i++) {
            int r = warp_m * 32 + i * 16 + (lane & 15) + rowoff;
            int c = kc + (lane >> 4);
            ldm_x4(a[i], smAb + SW128((uint32_t)(r * 128 + c * 16)));
        }
        uint32_t b[8][2];
        #pragma unroll
        for (int j2 = 0; j2 < 4; j2++) {
            int r = warp_n * 64 + j2 * 16 + (lane & 15);
            int c = kc + (lane >> 4);
            uint32_t t[4];
            ldm_x4(t, smBb + SW128((uint32_t)(r * 128 + c * 16)));
            b[j2 * 2][0] = t[0]; b[j2 * 2 + 1][0] = t[1];
            b[j2 * 2][1] = t[2]; b[j2 * 2 + 1][1] = t[3];
        }
        #pragma unroll
        for (int i = 0; i < 2; i++)
            #pragma unroll
            for (int j = 0; j < 8; j++)
                mma16816(acc[i][j], a[i], b[j]);
    }
}

// ---------------- zero scratch accumulators ----------------
__global__ void zero_kernel() {
    const size_t ns = (size_t)B_ * 128 * RES2;
    const size_t total = ns + (size_t)B_ * RES2;
    for (size_t i = (size_t)blockIdx.x * blockDim.x + threadIdx.x; i < total;
         i += (size_t)gridDim.x * blockDim.x) {
        if (i < ns) g_sums[i] = 0.f;
        else        g_cnt[i - ns] = 0.f;
    }
}

// ---------------- input NCHW fp32 -> channel-last bf16 hi/lo ----------------
__global__ void cvt_kernel(const float* __restrict__ src, int sel)
{
    __shared__ float s[64 * 65];
    uint32_t* dh = sel ? (uint32_t*)g_xah : (uint32_t*)g_x1h;
    uint32_t* dl = sel ? (uint32_t*)g_xal : (uint32_t*)g_x1l;
    int tid = threadIdx.x;
    int x0 = blockIdx.x * 64, y = blockIdx.y, b = blockIdx.z;
    #pragma unroll
    for (int i = 0; i < 16; i++) {
        int lin = tid + i * 256;
        int x = lin & 63, ci = lin >> 6;
        s[x * 65 + ci] = src[(((size_t)b * 64 + ci) * 256 + y) * 256 + x0 + x];
    }
    __syncthreads();
    #pragma unroll
    for (int i = 0; i < 8; i++) {
        int lin = tid + i * 256;
        int c2 = lin & 31, x = lin >> 5;
        float a = s[x * 65 + c2 * 2], bb = s[x * 65 + c2 * 2 + 1];
        uint32_t uh, ul; split2(a, bb, uh, ul);
        size_t o = (((size_t)b * 256 + y) * 256 + x0 + x) * 32 + c2;
        dh[o] = uh; dl[o] = ul;
    }
}

// ---------------- c_last -> bf16 hi/lo ----------------
__global__ void clconv_kernel(const float* __restrict__ clast)
{
    int i = blockIdx.x * blockDim.x + threadIdx.x;
    if (i >= NPTS * 32) return;
    float a = clast[2 * i], b = clast[2 * i + 1];
    uint32_t uh, ul;
    split2(a, b, uh, ul);
    ((uint32_t*)g_clh)[i] = uh;
    ((uint32_t*)g_cll)[i] = ul;
}

// ---------------- weight packing ----------------
__global__ void wconv_kernel(const float* __restrict__ W1, const float* __restrict__ W2,
                             const float* __restrict__ Wc, const float* __restrict__ WC1,
                             const float* __restrict__ WC2, const float* __restrict__ WX)
{
    int i = blockIdx.x * blockDim.x + threadIdx.x;
    if (i < 256 * 128) {            // fc1: [K=128][N=256] -> [N][K]
        int n = i >> 7, k = i & 127;
        float v = W1[k * 256 + n];
        __nv_bfloat16 h = __float2bfloat16(v);
        g_w1t_h[i] = h; g_w1t_l[i] = __float2bfloat16(v - __bfloat162float(h));
    }
    if (i < 128 * 256) {            // fc2
        int n = i >> 8, k = i & 255;
        float v = W2[k * 128 + n];
        __nv_bfloat16 h = __float2bfloat16(v);
        g_w2t_h[i] = h; g_w2t_l[i] = __float2bfloat16(v - __bfloat162float(h));
    }
    if (i < 128 * 64) {             // fcc
        int n = i >> 6, k = i & 63;
        float v = Wc[k * 128 + n];
        __nv_bfloat16 h = __float2bfloat16(v);
        g_wct_h[i] = h; g_wct_l[i] = __float2bfloat16(v - __bfloat162float(h));
    }
    if (i < 9 * 128 * 64) {         // conv1 OIHW -> [tap][co][ci]
        int t = i / 8192; int r = i - t * 8192; int co = r >> 6, ci = r & 63;
        float v = WC1[((size_t)(co * 64 + ci)) * 9 + t];
        __nv_bfloat16 h = __float2bfloat16(v);
        g_wc1h[i] = h; g_wc1l[i] = __float2bfloat16(v - __bfloat162float(h));
    }
    if (i < 9 * 128 * 128) {        // conv2 OIHW -> [tap][co][ci]
        int t = i / 16384; int r = i & 16383; int co = r >> 7, ci = r & 127;
        float v = WC2[((size_t)(co * 128 + ci)) * 9 + t];
        __nv_bfloat16 h = __float2bfloat16(v);
        g_wc2h[i] = h; g_wc2l[i] = __float2bfloat16(v - __bfloat162float(h));
    }
    if (i < 128 * 64) {             // conv1x1 [co][ci]
        float v = WX[i];
        __nv_bfloat16 h = __float2bfloat16(v);
        g_wxh[i] = h; g_wxl[i] = __float2bfloat16(v - __bfloat162float(h));
    }
}

// ---------------- conv staging ----------------
__device__ __forceinline__ void conv_stageA(char* smAp, const __nv_bfloat16* rowsrc,
                                            int x0, int rowok, int ldci, int tid)
{
    __syncthreads();
    for (int e = tid; e < 1040; e += 256) {
        int r = e >> 3, q = e & 7;
        int gx = x0 - 1 + r;
        uint4 v = make_uint4(0, 0, 0, 0);
        if (rowok && (unsigned)gx < 256u)
            v = *(const uint4*)(rowsrc + (size_t)gx * ldci + q * 8);
        *(uint4*)(smAp + SW128(r * 128 + q * 16)) = v;
    }
    __syncthreads();
}
__device__ __forceinline__ void conv_stageB(char* smBp, const __nv_bfloat16* wsrc,
                                            int ldw, int tid)
{
    __syncthreads();
    for (int e = tid; e < 1024; e += 256) {
        int r = e >> 3, q = e & 7;
        uint4 v = *(const uint4*)(wsrc + (size_t)r * ldw + q * 8);
        *(uint4*)(smBp + SW128(r * 128 + q * 16)) = v;
    }
    __syncthreads();
}

// ---------------- implicit-GEMM 3x3 conv via HMMA, 3-term bf16 split ----------------
// Block: 128 x-pixels (one row y) x 128 couts; 8 warps (4M x 2N).
template<int CIN, int LAYER>
__global__ __launch_bounds__(256)
void conv_hmma_kernel(const float* __restrict__ bias)
{
    __shared__ __align__(128) __nv_bfloat16 smA[130 * 64];
    __shared__ __align__(128) __nv_bfloat16 smB[128 * 64];
    char* smAp = (char*)smA; char* smBp = (char*)smB;
    uint32_t smAb = smem_u32(smA), smBb = smem_u32(smB);

    const __nv_bfloat16* inh = (LAYER == 1) ? g_x1h : g_c1h;
    const __nv_bfloat16* inl = (LAYER == 1) ? g_x1l : g_c1l;
    const __nv_bfloat16* wh  = (LAYER == 1) ? g_wc1h : g_wc2h;
    const __nv_bfloat16* wl  = (LAYER == 1) ? g_wc1l : g_wc2l;
    uint32_t* outh = (uint32_t*)((LAYER == 1) ? g_c1h : g_c2h);
    uint32_t* outl = (uint32_t*)((LAYER == 1) ? g_c1l : g_c2l);

    const int tid = threadIdx.x, lane = tid & 31, wid = tid >> 5;
    const int warp_m = wid & 3, warp_n = wid >> 2;
    const int x0 = blockIdx.x * 128;
    const int y = blockIdx.y;
    const int b = blockIdx.z;

    float acc[2][8][4] = {};

    for (int cc = 0; cc < CIN / 64; cc++) {
        for (int ky = 0; ky < 3; ky++) {
            int gy = y + ky - 1;
            int rowok = ((unsigned)gy < 256u) ? 1 : 0;
            size_t rb = (((size_t)b * 256 + (rowok ? gy : 0)) * 256) * CIN + cc * 64;
            // term hh and hl share A_h
            conv_stageA(smAp, inh + rb, x0, rowok, CIN, tid);
            for (int kx = 0; kx < 3; kx++) {
                conv_stageB(smBp, wh + ((size_t)(ky * 3 + kx) * 128) * CIN + cc * 64, CIN, tid);
                mma_block_pass(smAb, smBb, kx, warp_m, warp_n, lane, acc);
            }
            for (int kx = 0; kx < 3; kx++) {
                conv_stageB(smBp, wl + ((size_t)(ky * 3 + kx) * 128) * CIN + cc * 64, CIN, tid);
                mma_block_pass(smAb, smBb, kx, warp_m, warp_n, lane, acc);
            }
            // term lh
            conv_stageA(smAp, inl + rb, x0, rowok, CIN, tid);
            for (int kx = 0; kx < 3; kx++) {
                conv_stageB(smBp, wh + ((size_t)(ky * 3 + kx) * 128) * CIN + cc * 64, CIN, tid);
                mma_block_pass(smAb, smBb, kx, warp_m, warp_n, lane, acc);
            }
        }
    }

    // epilogue: bias + relu -> split hi/lo -> channel-last [pixel][128]
    const int g = lane >> 2, t4 = lane & 3;
    size_t pixbase = ((size_t)b * 256 + y) * 256 + x0;
    #pragma unroll
    for (int i = 0; i < 2; i++) {
        size_t pA = pixbase + warp_m * 32 + i * 16 + g;
        size_t pB = pA + 8;
        #pragma unroll
        for (int j = 0; j < 8; j++) {
            int col = warp_n * 64 + j * 8 + t4 * 2;
            float b0 = bias[col], b1v = bias[col + 1];
            uint32_t uh, ul;
            float v0 = fmaxf(acc[i][j][0] + b0, 0.f);
            float v1 = fmaxf(acc[i][j][1] + b1v, 0.f);
            split2(v0, v1, uh, ul);
            outh[pA * 64 + (col >> 1)] = uh;
            outl[pA * 64 + (col >> 1)] = ul;
            float v2 = fmaxf(acc[i][j][2] + b0, 0.f);
            float v3 = fmaxf(acc[i][j][3] + b1v, 0.f);
            split2(v2, v3, uh, ul);
            outh[pB * 64 + (col >> 1)] = uh;
            outl[pB * 64 + (col >> 1)] = ul;
        }
    }
}

// ---------------- fc-style GEMM staging chunk (validated R6 core) ----------------
__device__ __forceinline__ void gemm_chunk(
    char* smAp, char* smBp, uint32_t smAb, uint32_t smBb,
    const __nv_bfloat16* __restrict__ Ag, int lda, int m0,
    const __nv_bfloat16* __restrict__ Bg, int ldb, int n0, int koff,
    int tid, int warp_m, int warp_n, int lane,
    float acc[2][8][4])
{
    __syncthreads();
    for (int e = tid; e < 1024; e += 256) {
        int row = e >> 3, uc = e & 7;
        int grow = m0 + row;
        uint4 v = make_uint4(0, 0, 0, 0);
        if (grow < NPTS)
            v = *(const uint4*)(Ag + (size_t)grow * lda + koff + uc * 8);
        *(uint4*)(smAp + SW128(row * 128 + uc * 16)) = v;
    }
    for (int e = tid; e < 1024; e += 256) {
        int row = e >> 3, uc = e & 7;
        uint4 v = *(const uint4*)(Bg + (size_t)(n0 + row) * ldb + koff + uc * 8);
        *(uint4*)(smBp + SW128(row * 128 + uc * 16)) = v;
    }
    __syncthreads();
    mma_block_pass(smAb, smBb, 0, warp_m, warp_n, lane, acc);
}

// ---------------- fuse1x1: acc = x_ac @ Wx (3-term); out = relu_conv2 + acc + b1x1 ----------------
__global__ __launch_bounds__(256)
void fuse1x1_kernel(const float* __restrict__ bx)
{
    __shared__ __align__(128) __nv_bfloat16 smA[128 * 64];
    __shared__ __align__(128) __nv_bfloat16 smB[128 * 64];
    char* smAp = (char*)smA; char* smBp = (char*)smB;
    uint32_t smAb = smem_u32(smA), smBb = smem_u32(smB);

    const int tid = threadIdx.x, lane = tid & 31, wid = tid >> 5;
    const int warp_m = wid & 3, warp_n = wid >> 2;
    const int m0 = blockIdx.x * 128;

    float acc[2][8][4] = {};
    const __nv_bfloat16* Aph[3] = {g_xah, g_xal, g_xah};
    const __nv_bfloat16* Bph[3] = {g_wxh, g_wxh, g_wxl};
    for (int ph = 0; ph < 3; ph++)
        gemm_chunk(smAp, smBp, smAb, smBb, Aph[ph], 64, m0,
                   Bph[ph], 64, 0, 0, tid, warp_m, warp_n, lane, acc);

    const uint32_t* c2h = (const uint32_t*)g_c2h;
    const uint32_t* c2l = (const uint32_t*)g_c2l;
    const int g = lane >> 2, t4 = lane & 3;
    #pragma unroll
    for (int i = 0; i < 2; i++) {
        size_t pA = (size_t)m0 + warp_m * 32 + i * 16 + g;
        size_t pB = pA + 8;
        #pragma unroll
        for (int j = 0; j < 8; j++) {
            int col = warp_n * 64 + j * 8 + t4 * 2;
            float bb0 = bx[col], bb1 = bx[col + 1];
            uint32_t ph = c2h[pA * 64 + (col >> 1)], pl = c2l[pA * 64 + (col >> 1)];
            float f0 = bf2f_lo(ph) + bf2f_lo(pl);
            float f1 = bf2f_hi(ph) + bf2f_hi(pl);
            *(float2*)&g_xat[pA * 128 + col] =
                make_float2(acc[i][j][0] + bb0 + f0, acc[i][j][1] + bb1 + f1);
            uint32_t qh = c2h[pB * 64 + (col >> 1)], ql = c2l[pB * 64 + (col >> 1)];
            float f2 = bf2f_lo(qh) + bf2f_lo(ql);
            float f3 = bf2f_hi(qh) + bf2f_hi(ql);
            *(float2*)&g_xat[pB * 128 + col] =
                make_float2(acc[i][j][2] + bb0 + f2, acc[i][j][3] + bb1 + f3);
        }
    }
}

// ---------------- g_xat [b][y][x][c] -> x_after NCHW fp32 ----------------
__global__ void xat2nchw_kernel(float* __restrict__ dst)
{
    __shared__ float s[32 * 33];
    int tid = threadIdx.x;
    int x0 = blockIdx.x * 32, y = blockIdx.y;
    int b = blockIdx.z >> 2, c0 = (blockIdx.z & 3) * 32;
    #pragma unroll
    for (int i = 0; i < 4; i++) {
        int lin = tid + i * 256;
        int c = lin & 31, x = lin >> 5;
        s[x * 33 + c] = g_xat[(((size_t)b * 256 + y) * 256 + x0 + x) * 128 + c0 + c];
    }
    __syncthreads();
    #pragma unroll
    for (int i = 0; i < 4; i++) {
        int lin = tid + i * 256;
        int x = lin & 31, c = lin >> 5;
        dst[(((size_t)b * 128 + c0 + c) * 256 + y) * 256 + x0 + x] = s[x * 33 + c];
    }
}

// ---------------- bilinear sampling (reads g_xat fp32) ----------------
__global__ void sample_kernel(const float* __restrict__ p)
{
    int gid  = blockIdx.x * blockDim.x + threadIdx.x;
    int wid  = gid >> 5;
    int lane = gid & 31;
    if (wid >= NPTS) return;
    int b = (wid >= N_) ? 1 : 0;

    float sx = p[(size_t)wid * 3 + 0];
    float sy = p[(size_t)wid * 3 + 1];
    float px = fminf(fmaxf(sx * 255.f, 0.f), 255.f);
    float py = fminf(fmaxf(sy * 255.f, 0.f), 255.f);
    float x0f = floorf(px), y0f = floorf(py);
    int x0 = (int)x0f, y0 = (int)y0f;
    int x1 = min(x0 + 1, 255), y1 = min(y0 + 1, 255);
    float wx = px - x0f, wy = py - y0f;
    float w00 = (1.f - wx) * (1.f - wy);
    float w01 = wx * (1.f - wy);
    float w10 = (1.f - wx) * wy;
    float w11 = wx * wy;

    const float4* F = (const float4*)g_xat;
    size_t r00 = ((size_t)(b * 256 + y0) * 256 + x0) * 32 + lane;
    size_t r01 = ((size_t)(b * 256 + y0) * 256 + x1) * 32 + lane;
    size_t r10 = ((size_t)(b * 256 + y1) * 256 + x0) * 32 + lane;
    size_t r11 = ((size_t)(b * 256 + y1) * 256 + x1) * 32 + lane;
    float4 f00 = F[r00], f01 = F[r01], f10 = F[r10], f11 = F[r11];
    float4 r;
    r.x = f00.x * w00 + f01.x * w01 + f10.x * w10 + f11.x * w11;
    r.y = f00.y * w00 + f01.y * w01 + f10.y * w10 + f11.y * w11;
    r.z = f00.z * w00 + f01.z * w01 + f10.z * w10 + f11.z * w11;
    r.w = f00.w * w00 + f01.w * w01 + f10.w * w10 + f11.w * w11;

    uint32_t h0, l0, h1, l1;
    split2(r.x, r.y, h0, l0);
    split2(r.z, r.w, h1, l1);
    uint32_t* ch = (uint32_t*)g_c0h;
    uint32_t* cl = (uint32_t*)g_c0l;
    size_t base = (size_t)wid * 64 + lane * 2;
    ch[base] = h0; ch[base + 1] = h1;
    cl[base] = l0; cl[base + 1] = l1;

    if (lane == 0) {
        int ix = min(max((int)(sx * 256.f), 0), 255);
        int iy = min(max((int)(sy * 256.f), 0), 255);
        int idx = ix + (iy << 8);
        g_idx[wid] = idx;
        atomicAdd(&g_cnt[b * RES2 + idx], 1.f);
    }
}

// ---------------- fc1: t = relu(c0 @ W1 + b1), 3-term bf16 split ----------------
__global__ __launch_bounds__(256)
void fc1_hmma_kernel(const float* __restrict__ bias)
{
    __shared__ __align__(128) __nv_bfloat16 smA[128 * 64];
    __shared__ __align__(128) __nv_bfloat16 smB[128 * 64];
    char* smAp = (char*)smA; char* smBp = (char*)smB;
    uint32_t smAb = smem_u32(smA), smBb = smem_u32(smB);

    const int tid = threadIdx.x, lane = tid & 31, wid = tid >> 5;
    const int warp_m = wid & 3, warp_n = wid >> 2;
    const int m0 = blockIdx.x * 128, n0 = blockIdx.y * 128;

    float acc[2][8][4] = {};
    const __nv_bfloat16* Aph[3] = {g_c0h, g_c0l, g_c0h};
    const __nv_bfloat16* Bph[3] = {g_w1t_h, g_w1t_h, g_w1t_l};
    for (int ph = 0; ph < 3; ph++)
        for (int kc = 0; kc < 2; kc++)
            gemm_chunk(smAp, smBp, smAb, smBb, Aph[ph], 128, m0,
                       Bph[ph], 128, n0, kc * 64, tid, warp_m, warp_n, lane, acc);

    uint32_t* th = (uint32_t*)g_th;
    uint32_t* tl = (uint32_t*)g_tl;
    const int g = lane >> 2, t4 = lane & 3;
    #pragma unroll
    for (int i = 0; i < 2; i++) {
        int rowA = m0 + warp_m * 32 + i * 16 + g;
        int rowB = rowA + 8;
        #pragma unroll
        for (int j = 0; j < 8; j++) {
            int col = n0 + warp_n * 64 + j * 8 + t4 * 2;
            float b0 = bias[col], b1 = bias[col + 1];
            if (rowA < NPTS) {
                float v0 = fmaxf(acc[i][j][0] + b0, 0.f);
                float v1 = fmaxf(acc[i][j][1] + b1, 0.f);
                uint32_t uh, ul; split2(v0, v1, uh, ul);
                size_t o = (size_t)rowA * 128 + (col >> 1);
                th[o] = uh; tl[o] = ul;
            }
            if (rowB < NPTS) {
                float v2 = fmaxf(acc[i][j][2] + b0, 0.f);
                float v3 = fmaxf(acc[i][j][3] + b1, 0.f);
                uint32_t uh, ul; split2(v2, v3, uh, ul);
                size_t o = (size_t)rowB * 128 + (col >> 1);
                th[o] = uh; tl[o] = ul;
            }
        }
    }
}

// ---------------- fc2: c = t@W2 + b2 + c_last@Wc + bc; write c; scatter-add ----------------
__global__ __launch_bounds__(256)
void fc2_hmma_kernel(const float* __restrict__ b2, const float* __restrict__ bc,
                     float* __restrict__ outc)
{
    __shared__ __align__(128) __nv_bfloat16 smA[128 * 64];
    __shared__ __align__(128) __nv_bfloat16 smB[128 * 64];
    char* smAp = (char*)smA; char* smBp = (char*)smB;
    uint32_t smAb = smem_u32(smA), smBb = smem_u32(smB);

    const int tid = threadIdx.x, lane = tid & 31, wid = tid >> 5;
    const int warp_m = wid & 3, warp_n = wid >> 2;
    const int m0 = blockIdx.x * 128;

    float acc[2][8][4] = {};
    const __nv_bfloat16* Aph[6] = {g_th, g_tl, g_th, g_clh, g_cll, g_clh};
    const __nv_bfloat16* Bph[6] = {g_w2t_h, g_w2t_h, g_w2t_l, g_wct_h, g_wct_h, g_wct_l};
    const int ldp[6] = {256, 256, 256, 64, 64, 64};
    const int ncp[6] = {4, 4, 4, 1, 1, 1};
    for (int ph = 0; ph < 6; ph++)
        for (int kc = 0; kc < ncp[ph]; kc++)
            gemm_chunk(smAp, smBp, smAb, smBb, Aph[ph], ldp[ph], m0,
                       Bph[ph], ldp[ph], 0, kc * 64, tid, warp_m, warp_n, lane, acc);

    const int g = lane >> 2, t4 = lane & 3;
    int rows[4], idxs[4], bbs[4];
    #pragma unroll
    for (int i = 0; i < 2; i++) {
        rows[i * 2]     = m0 + warp_m * 32 + i * 16 + g;
        rows[i * 2 + 1] = rows[i * 2] + 8;
    }
    #pragma unroll
    for (int k = 0; k < 4; k++) {
        idxs[k] = 0; bbs[k] = 0;
        if (rows[k] < NPTS) { idxs[k] = g_idx[rows[k]]; bbs[k] = (rows[k] >= N_) ? 1 : 0; }
    }
    #pragma unroll
    for (int i = 0; i < 2; i++) {
        #pragma unroll
        for (int j = 0; j < 8; j++) {
            int col = warp_n * 64 + j * 8 + t4 * 2;
            float bb0 = b2[col] + bc[col], bb1 = b2[col + 1] + bc[col + 1];
            int rA = rows[i * 2], rB = rows[i * 2 + 1];
            float v0 = acc[i][j][0] + bb0, v1 = acc[i][j][1] + bb1;
            float v2 = acc[i][j][2] + bb0, v3 = acc[i][j][3] + bb1;
            if (rA < NPTS) {
                *(float2*)(outc + (size_t)rA * 128 + col) = make_float2(v0, v1);
                int ia = idxs[i * 2], ba = bbs[i * 2];
                atomicAdd(&g_sums[((size_t)(ba * 128 + col)) * RES2 + ia], v0);
                atomicAdd(&g_sums[((size_t)(ba * 128 + col + 1)) * RES2 + ia], v1);
            }
            if (rB < NPTS) {
                *(float2*)(outc + (size_t)rB * 128 + col) = make_float2(v2, v3);
                int ib = idxs[i * 2 + 1], bbx = bbs[i * 2 + 1];
                atomicAdd(&g_sums[((size_t)(bbx * 128 + col)) * RES2 + ib], v2);
                atomicAdd(&g_sums[((size_t)(bbx * 128 + col + 1)) * RES2 + ib], v3);
            }
        }
    }
}

// ---------------- plane finalize + maxpool ----------------
__global__ void plane_kernel(float* __restrict__ dout)
{
    int i = blockIdx.x * blockDim.x + threadIdx.x;
    if (i >= B_ * 128 * RES2) return;
    int b = i >> 23;
    int idx = i & 65535;
    float cnt = g_cnt[(b << 16) + idx];
    dout[BP_OFF + i] = g_sums[i] / fmaxf(cnt, 1.f);
}

__global__ void pool_kernel(float* __restrict__ dout)
{
    int i = blockIdx.x * blockDim.x + threadIdx.x;
    if (i >= B_ * 128 * 128 * 128) return;
    int px = i & 127, py = (i >> 7) & 127, bc = i >> 14;
    const float* pl = dout + BP_OFF + (size_t)bc * RES2;
    int r0 = (py * 2) * 256 + px * 2;
    float v = fmaxf(fmaxf(pl[r0], pl[r0 + 1]), fmaxf(pl[r0 + 256], pl[r0 + 257]));
    dout[OUT_OFF + i] = v;
}

// ---------------- launch ----------------
extern "C" void kernel_launch(void* const* d_in, const int* in_sizes, int n_in,
                              void* d_out, int out_size)
{
    const float* p     = (const float*)d_in[0];
    const float* x_xy  = (const float*)d_in[1];
    const float* x_ac  = (const float*)d_in[2];
    const float* clast = (const float*)d_in[3];
    const float* w1    = (const float*)d_in[4];
    const float* bb1   = (const float*)d_in[5];
    const float* w2    = (const float*)d_in[6];
    const float* bb2   = (const float*)d_in[7];
    const float* w1x1  = (const float*)d_in[8];
    const float* b1x1  = (const float*)d_in[9];
    const float* wfc1  = (const float*)d_in[10];
    const float* bfc1  = (const float*)d_in[11];
    const float* wfc2  = (const float*)d_in[12];
    const float* bfc2  = (const float*)d_in[13];
    const float* wfcc  = (const float*)d_in[14];
    const float* bfcc  = (const float*)d_in[15];
    float* out = (float*)d_out;

    zero_kernel<<<2048, 256>>>();
    wconv_kernel<<<576, 256>>>(wfc1, wfc2, wfcc, w1, w2, w1x1);
    clconv_kernel<<<(NPTS * 32 + 255) / 256, 256>>>(clast);
    cvt_kernel<<<dim3(4, 256, 2), 256>>>(x_xy, 0);
    cvt_kernel<<<dim3(4, 256, 2), 256>>>(x_ac, 1);
    conv_hmma_kernel<64, 1><<<dim3(2, 256, 2), 256>>>(bb1);
    conv_hmma_kernel<128, 2><<<dim3(2, 256, 2), 256>>>(bb2);
    fuse1x1_kernel<<<NPIX / 128, 256>>>(b1x1);
    xat2nchw_kernel<<<dim3(8, 256, 8), 256>>>(out + XA_OFF);
    sample_kernel<<<(NPTS * 32 + 255) / 256, 256>>>(p);
    fc1_hmma_kernel<<<dim3(MTILES, 2), 256>>>(bfc1);
    fc2_hmma_kernel<<<dim3(MTILES, 1), 256>>>(bfc2, bfcc, out + C_OFF);
    plane_kernel<<<(B_ * 128 * RES2) / 256, 256>>>(out);
    pool_kernel<<<(B_ * 128 * 128 * 128) / 256, 256>>>(out);
}

// round 11
// speedup vs baseline: 1.2372x; 1.2229x over previous
#include <cuda_runtime.h>
#include <cuda_bf16.h>
#include <cstdint>

// Problem constants
#define B_      2
#define N_      100000
#define NPTS    (B_ * N_)          // 200000
#define RES     256
#define RES2    65536
#define NPIX    (B_ * RES * RES)   // 131072

// Output layout (concatenated, return order: out, before_pool, x_after, c)
#define OUT_OFF 0
#define BP_OFF  4194304            // 2*128*128*128
#define XA_OFF  20971520           // BP_OFF + 2*128*256*256
#define C_OFF   37748736           // XA_OFF + 2*128*256*256

#define MTILES  1563               // ceil(200000/128)

// ---------------- device scratch ----------------
__device__ __align__(128) float g_xat[(size_t)NPIX * 128];     // x_after [b][y][x][c] fp32
__device__ __align__(128) float g_sums[(size_t)B_ * 128 * RES2];
__device__ __align__(128) float g_cnt[(size_t)B_ * RES2];
__device__ __align__(128) int   g_idx[NPTS];

// channel-last bf16 hi/lo activations
__device__ __align__(128) __nv_bfloat16 g_x1h[(size_t)NPIX * 64];
__device__ __align__(128) __nv_bfloat16 g_x1l[(size_t)NPIX * 64];
__device__ __align__(128) __nv_bfloat16 g_xah[(size_t)NPIX * 64];
__device__ __align__(128) __nv_bfloat16 g_xal[(size_t)NPIX * 64];
__device__ __align__(128) __nv_bfloat16 g_c1h[(size_t)NPIX * 128];
__device__ __align__(128) __nv_bfloat16 g_c1l[(size_t)NPIX * 128];
__device__ __align__(128) __nv_bfloat16 g_c2h[(size_t)NPIX * 128];
__device__ __align__(128) __nv_bfloat16 g_c2l[(size_t)NPIX * 128];

// point-pipeline bf16 hi/lo
__device__ __align__(128) __nv_bfloat16 g_c0h[(size_t)NPTS * 128];
__device__ __align__(128) __nv_bfloat16 g_c0l[(size_t)NPTS * 128];
__device__ __align__(128) __nv_bfloat16 g_th [(size_t)NPTS * 256];
__device__ __align__(128) __nv_bfloat16 g_tl [(size_t)NPTS * 256];
__device__ __align__(128) __nv_bfloat16 g_clh[(size_t)NPTS * 64];
__device__ __align__(128) __nv_bfloat16 g_cll[(size_t)NPTS * 64];

// packed weights bf16 hi/lo
__device__ __align__(128) __nv_bfloat16 g_w1t_h[256 * 128];
__device__ __align__(128) __nv_bfloat16 g_w1t_l[256 * 128];
__device__ __align__(128) __nv_bfloat16 g_w2t_h[128 * 256];
__device__ __align__(128) __nv_bfloat16 g_w2t_l[128 * 256];
__device__ __align__(128) __nv_bfloat16 g_wct_h[128 * 64];
__device__ __align__(128) __nv_bfloat16 g_wct_l[128 * 64];
__device__ __align__(128) __nv_bfloat16 g_wc1h[9 * 128 * 64];
__device__ __align__(128) __nv_bfloat16 g_wc1l[9 * 128 * 64];
__device__ __align__(128) __nv_bfloat16 g_wc2h[9 * 128 * 128];
__device__ __align__(128) __nv_bfloat16 g_wc2l[9 * 128 * 128];
__device__ __align__(128) __nv_bfloat16 g_wxh[128 * 64];
__device__ __align__(128) __nv_bfloat16 g_wxl[128 * 64];

// ---------------- helpers ----------------
__device__ __forceinline__ uint32_t smem_u32(const void* p) {
    uint32_t a;
    asm("{ .reg .u64 t; cvta.to.shared.u64 t, %1; cvt.u32.u64 %0, t; }" : "=r"(a) : "l"(p));
    return a;
}
#define SW128(o) ((o) ^ (((o) >> 3) & 0x70))

#define CP16(dst, src, n) asm volatile("cp.async.cg.shared.global [%0], [%1], 16, %2;" :: "r"(dst), "l"(src), "r"(n))
#define CPCOMMIT() asm volatile("cp.async.commit_group;" ::: "memory")
#define CPWAIT0()  asm volatile("cp.async.wait_group 0;" ::: "memory")
#define CPWAIT1()  asm volatile("cp.async.wait_group 1;" ::: "memory")

__device__ __forceinline__ void ldm_x4(uint32_t* r, uint32_t addr) {
    asm volatile("ldmatrix.sync.aligned.m8n8.x4.shared.b16 {%0,%1,%2,%3}, [%4];"
        : "=r"(r[0]), "=r"(r[1]), "=r"(r[2]), "=r"(r[3]) : "r"(addr));
}
__device__ __forceinline__ void mma16816(float* c, const uint32_t* a, const uint32_t* b) {
    asm volatile("mma.sync.aligned.m16n8k16.row.col.f32.bf16.bf16.f32 "
        "{%0,%1,%2,%3}, {%4,%5,%6,%7}, {%8,%9}, {%0,%1,%2,%3};"
        : "+f"(c[0]), "+f"(c[1]), "+f"(c[2]), "+f"(c[3])
        : "r"(a[0]), "r"(a[1]), "r"(a[2]), "r"(a[3]), "r"(b[0]), "r"(b[1]));
}

__device__ __forceinline__ void split2(float a, float b, uint32_t& uh, uint32_t& ul) {
    __nv_bfloat16 ha = __float2bfloat16(a), hb = __float2bfloat16(b);
    float ra = a - __bfloat162float(ha), rb = b - __bfloat162float(hb);
    __nv_bfloat16 la = __float2bfloat16(ra), lb = __float2bfloat16(rb);
    uh = ((uint32_t)__bfloat16_as_ushort(hb) << 16) | __bfloat16_as_ushort(ha);
    ul = ((uint32_t)__bfloat16_as_ushort(lb) << 16) | __bfloat16_as_ushort(la);
}
__device__ __forceinline__ float bf2f_lo(uint32_t u) {
    return __bfloat162float(__ushort_as_bfloat16((unsigned short)(u & 0xFFFF)));
}
__device__ __forceinline__ float bf2f_hi(uint32_t u) {
    return __bfloat162float(__ushort_as_bfloat16((unsigned short)(u >> 16)));
}

// warp-level compute: block tile Mx128 (N=64 per warp_n), K=64
__device__ __forceinline__ void mma_pass64(uint32_t smAb, uint32_t smBb, int rowoff,
                                           int warp_m, int warp_n, int lane,
                                           float acc[2][8][4])
{
    #pragma unroll
    for (int ks = 0; ks < 4; ks++) {
        int kc = ks * 2;
        uint32_t a[2][4];
        #pragma unroll
        for (int i = 0; i < 2; i++) {
            int r = warp_m * 32 + i * 16 + (lane & 15) + rowoff;
            int c = kc + (lane >> 4);
            ldm_x4(a[i], smAb + SW128((uint32_t)(r * 128 + c * 16)));
        }
        uint32_t b[8][2];
        #pragma unroll
        for (int j2 = 0; j2 < 4; j2++) {
            int r = warp_n * 64 + j2 * 16 + (lane & 15);
            int c = kc + (lane >> 4);
            uint32_t t[4];
            ldm_x4(t, smBb + SW128((uint32_t)(r * 128 + c * 16)));
            b[j2 * 2][0] = t[0]; b[j2 * 2 + 1][0] = t[1];
            b[j2 * 2][1] = t[2]; b[j2 * 2 + 1][1] = t[3];
        }
        #pragma unroll
        for (int i = 0; i < 2; i++)
            #pragma unroll
            for (int j = 0; j < 8; j++)
                mma16816(acc[i][j], a[i], b[j]);
    }
}

// warp-level compute: N=32 per warp_n (conv co-split), K=64
__device__ __forceinline__ void mma_pass32(uint32_t smAb, uint32_t smBb, int rowoff,
                                           int warp_m, int warp_n, int lane,
                                           float acc[2][4][4])
{
    #pragma unroll
    for (int ks = 0; ks < 4; ks++) {
        int kc = ks * 2;
        uint32_t a[2][4];
        #pragma unroll
        for (int i = 0; i < 2; i++) {
            int r = warp_m * 32 + i * 16 + (lane & 15) + rowoff;
            int c = kc + (lane >> 4);
            ldm_x4(a[i], smAb + SW128((uint32_t)(r * 128 + c * 16)));
        }
        uint32_t b[4][2];
        #pragma unroll
        for (int j2 = 0; j2 < 2; j2++) {
            int r = warp_n * 32 + j2 * 16 + (lane & 15);
            int c = kc + (lane >> 4);
            uint32_t t[4];
            ldm_x4(t, smBb + SW128((uint32_t)(r * 128 + c * 16)));
            b[j2 * 2][0] = t[0]; b[j2 * 2 + 1][0] = t[1];
            b[j2 * 2][1] = t[2]; b[j2 * 2 + 1][1] = t[3];
        }
        #pragma unroll
        for (int i = 0; i < 2; i++)
            #pragma unroll
            for (int j = 0; j < 4; j++)
                mma16816(acc[i][j], a[i], b[j]);
    }
}

// async A-tile stage [128][64]
__device__ __forceinline__ void stageA_async(uint32_t smA, const __nv_bfloat16* Ag,
                                             int lda, int m0, int mmax, int koff, int tid)
{
    for (int e = tid; e < 1024; e += 256) {
        int row = e >> 3, uc = e & 7;
        int grow = m0 + row;
        int ok = (grow < mmax) ? 16 : 0;
        const char* src = (const char*)(Ag + (ok ? ((size_t)grow * lda + koff + uc * 8) : 0));
        CP16(smA + SW128(row * 128 + uc * 16), src, ok);
    }
}
// sync B-tile stage [128][64] (L2-hot weights)
__device__ __forceinline__ void stageB_sync(char* smBp, const __nv_bfloat16* Bg,
                                            int ldb, int koff, int tid)
{
    for (int e = tid; e < 1024; e += 256) {
        int row = e >> 3, uc = e & 7;
        uint4 v = *(const uint4*)(Bg + (size_t)row * ldb + koff + uc * 8);
        *(uint4*)(smBp + SW128(row * 128 + uc * 16)) = v;
    }
}

// ---------------- zero scratch accumulators ----------------
__global__ void zero_kernel() {
    const size_t ns = (size_t)B_ * 128 * RES2;
    const size_t total = ns + (size_t)B_ * RES2;
    for (size_t i = (size_t)blockIdx.x * blockDim.x + threadIdx.x; i < total;
         i += (size_t)gridDim.x * blockDim.x) {
        if (i < ns) g_sums[i] = 0.f;
        else        g_cnt[i - ns] = 0.f;
    }
}

// ---------------- input NCHW fp32 -> channel-last bf16 hi/lo ----------------
__global__ void cvt_kernel(const float* __restrict__ src, int sel)
{
    __shared__ float s[64 * 65];
    uint32_t* dh = sel ? (uint32_t*)g_xah : (uint32_t*)g_x1h;
    uint32_t* dl = sel ? (uint32_t*)g_xal : (uint32_t*)g_x1l;
    int tid = threadIdx.x;
    int x0 = blockIdx.x * 64, y = blockIdx.y, b = blockIdx.z;
    #pragma unroll
    for (int i = 0; i < 16; i++) {
        int lin = tid + i * 256;
        int x = lin & 63, ci = lin >> 6;
        s[x * 65 + ci] = src[(((size_t)b * 64 + ci) * 256 + y) * 256 + x0 + x];
    }
    __syncthreads();
    #pragma unroll
    for (int i = 0; i < 8; i++) {
        int lin = tid + i * 256;
        int c2 = lin & 31, x = lin >> 5;
        float a = s[x * 65 + c2 * 2], bb = s[x * 65 + c2 * 2 + 1];
        uint32_t uh, ul; split2(a, bb, uh, ul);
        size_t o = (((size_t)b * 256 + y) * 256 + x0 + x) * 32 + c2;
        dh[o] = uh; dl[o] = ul;
    }
}

// ---------------- c_last -> bf16 hi/lo ----------------
__global__ void clconv_kernel(const float* __restrict__ clast)
{
    int i = blockIdx.x * blockDim.x + threadIdx.x;
    if (i >= NPTS * 32) return;
    float a = clast[2 * i], b = clast[2 * i + 1];
    uint32_t uh, ul;
    split2(a, b, uh, ul);
    ((uint32_t*)g_clh)[i] = uh;
    ((uint32_t*)g_cll)[i] = ul;
}

// ---------------- weight packing ----------------
__global__ void wconv_kernel(const float* __restrict__ W1, const float* __restrict__ W2,
                             const float* __restrict__ Wc, const float* __restrict__ WC1,
                             const float* __restrict__ WC2, const float* __restrict__ WX)
{
    int i = blockIdx.x * blockDim.x + threadIdx.x;
    if (i < 256 * 128) {
        int n = i >> 7, k = i & 127;
        float v = W1[k * 256 + n];
        __nv_bfloat16 h = __float2bfloat16(v);
        g_w1t_h[i] = h; g_w1t_l[i] = __float2bfloat16(v - __bfloat162float(h));
    }
    if (i < 128 * 256) {
        int n = i >> 8, k = i & 255;
        float v = W2[k * 128 + n];
        __nv_bfloat16 h = __float2bfloat16(v);
        g_w2t_h[i] = h; g_w2t_l[i] = __float2bfloat16(v - __bfloat162float(h));
    }
    if (i < 128 * 64) {
        int n = i >> 6, k = i & 63;
        float v = Wc[k * 128 + n];
        __nv_bfloat16 h = __float2bfloat16(v);
        g_wct_h[i] = h; g_wct_l[i] = __float2bfloat16(v - __bfloat162float(h));
    }
    if (i < 9 * 128 * 64) {
        int t = i / 8192; int r = i - t * 8192; int co = r >> 6, ci = r & 63;
        float v = WC1[((size_t)(co * 64 + ci)) * 9 + t];
        __nv_bfloat16 h = __float2bfloat16(v);
        g_wc1h[i] = h; g_wc1l[i] = __float2bfloat16(v - __bfloat162float(h));
    }
    if (i < 9 * 128 * 128) {
        int t = i / 16384; int r = i & 16383; int co = r >> 7, ci = r & 127;
        float v = WC2[((size_t)(co * 128 + ci)) * 9 + t];
        __nv_bfloat16 h = __float2bfloat16(v);
        g_wc2h[i] = h; g_wc2l[i] = __float2bfloat16(v - __bfloat162float(h));
    }
    if (i < 128 * 64) {
        float v = WX[i];
        __nv_bfloat16 h = __float2bfloat16(v);
        g_wxh[i] = h; g_wxl[i] = __float2bfloat16(v - __bfloat162float(h));
    }
}

// ---------------- conv group: A staged async, B taps double-buffered ----------------
__device__ __forceinline__ void conv_run_group(
    uint32_t aAddr, uint32_t bA0, uint32_t bA1,
    const __nv_bfloat16* Arow, int x0, int rowok, int ld,
    const __nv_bfloat16* const* bs, int nb,
    int tid, int warp_m, int warp_n, int lane, float acc[2][4][4])
{
    // A halo tile [130][64]
    for (int e = tid; e < 1040; e += 256) {
        int r = e >> 3, q = e & 7;
        int gx = x0 - 1 + r;
        int ok = (rowok && (unsigned)gx < 256u) ? 16 : 0;
        const char* src = (const char*)(Arow + (ok ? ((size_t)gx * ld + q * 8) : 0));
        CP16(aAddr + SW128(r * 128 + q * 16), src, ok);
    }
    // B0 tile [64 co][64 ci]
    for (int e = tid; e < 512; e += 256) {
        int r = e >> 3, q = e & 7;
        CP16(bA0 + SW128(r * 128 + q * 16), (const char*)(bs[0] + (size_t)r * ld + q * 8), 16);
    }
    CPCOMMIT(); CPWAIT0();
    __syncthreads();
    uint32_t bb[2] = {bA0, bA1};
    for (int j = 0; j < nb; j++) {
        if (j + 1 < nb) {
            uint32_t d = bb[(j + 1) & 1];
            for (int e = tid; e < 512; e += 256) {
                int r = e >> 3, q = e & 7;
                CP16(d + SW128(r * 128 + q * 16),
                     (const char*)(bs[j + 1] + (size_t)r * ld + q * 8), 16);
            }
            CPCOMMIT();
        }
        mma_pass32(aAddr, bb[j & 1], j % 3, warp_m, warp_n, lane, acc);
        if (j + 1 < nb) CPWAIT0();
        __syncthreads();
    }
}

// ---------------- implicit-GEMM 3x3 conv via HMMA (co-split halves) ----------------
template<int CIN, int LAYER>
__global__ __launch_bounds__(256)
void conv_hmma_kernel(const float* __restrict__ bias)
{
    __shared__ __align__(128) __nv_bfloat16 smA[130 * 64];      // 16640 B
    __shared__ __align__(128) __nv_bfloat16 smB[2][64 * 64];    // 16384 B
    uint32_t aAddr = smem_u32(smA);
    uint32_t bA0 = smem_u32(smB[0]), bA1 = smem_u32(smB[1]);

    const __nv_bfloat16* inh = (LAYER == 1) ? g_x1h : g_c1h;
    const __nv_bfloat16* inl = (LAYER == 1) ? g_x1l : g_c1l;
    const __nv_bfloat16* wh  = (LAYER == 1) ? g_wc1h : g_wc2h;
    const __nv_bfloat16* wl  = (LAYER == 1) ? g_wc1l : g_wc2l;
    uint32_t* outh = (uint32_t*)((LAYER == 1) ? g_c1h : g_c2h);
    uint32_t* outl = (uint32_t*)((LAYER == 1) ? g_c1l : g_c2l);

    const int tid = threadIdx.x, lane = tid & 31, wid = tid >> 5;
    const int warp_m = wid & 3, warp_n = wid >> 2;
    const int x0 = blockIdx.x * 128;
    const int y = blockIdx.y;
    const int b = blockIdx.z >> 1;
    const int coh = blockIdx.z & 1;

    float acc[2][4][4] = {};

    for (int cc = 0; cc < CIN / 64; cc++) {
        for (int ky = 0; ky < 3; ky++) {
            int gy = y + ky - 1;
            int rowok = ((unsigned)gy < 256u) ? 1 : 0;
            size_t rb = (((size_t)b * 256 + (rowok ? gy : 0)) * 256) * CIN + cc * 64;
            const __nv_bfloat16* bs6[6];
            const __nv_bfloat16* bs3[3];
            for (int kx = 0; kx < 3; kx++) {
                size_t wo = ((size_t)(ky * 3 + kx) * 128 + coh * 64) * CIN + cc * 64;
                bs6[kx] = wh + wo; bs6[kx + 3] = wl + wo; bs3[kx] = wh + wo;
            }
            conv_run_group(aAddr, bA0, bA1, inh + rb, x0, rowok, CIN,
                           bs6, 6, tid, warp_m, warp_n, lane, acc);
            conv_run_group(aAddr, bA0, bA1, inl + rb, x0, rowok, CIN,
                           bs3, 3, tid, warp_m, warp_n, lane, acc);
        }
    }

    // epilogue: bias + relu -> split hi/lo -> channel-last
    const int g = lane >> 2, t4 = lane & 3;
    size_t pixbase = ((size_t)b * 256 + y) * 256 + x0;
    #pragma unroll
    for (int i = 0; i < 2; i++) {
        size_t pA = pixbase + warp_m * 32 + i * 16 + g;
        size_t pB = pA + 8;
        #pragma unroll
        for (int j = 0; j < 4; j++) {
            int col = coh * 64 + warp_n * 32 + j * 8 + t4 * 2;
            float b0 = bias[col], b1v = bias[col + 1];
            uint32_t uh, ul;
            float v0 = fmaxf(acc[i][j][0] + b0, 0.f);
            float v1 = fmaxf(acc[i][j][1] + b1v, 0.f);
            split2(v0, v1, uh, ul);
            outh[pA * 64 + (col >> 1)] = uh;
            outl[pA * 64 + (col >> 1)] = ul;
            float v2 = fmaxf(acc[i][j][2] + b0, 0.f);
            float v3 = fmaxf(acc[i][j][3] + b1v, 0.f);
            split2(v2, v3, uh, ul);
            outh[pB * 64 + (col >> 1)] = uh;
            outl[pB * 64 + (col >> 1)] = ul;
        }
    }
}

// ---------------- generic grouped fc GEMM driver (A async double-buffered) ----------------
// Per group: one A tile (128x64), 1-2 B chunks staged synchronously from L2.
struct FcGroup {
    const __nv_bfloat16* A;
    const __nv_bfloat16* B0;
    const __nv_bfloat16* B1;   // nullptr if nb==1
    int ld;                    // lda == ldb
    int koff;
};

__device__ __forceinline__ void fc_run(const FcGroup* gs, int ng, int m0, int mmax, int n0,
                                       uint32_t aA0, uint32_t aA1, char* smBp,
                                       int tid, int warp_m, int warp_n, int lane,
                                       float acc[2][8][4])
{
    uint32_t aA[2] = {aA0, aA1};
    stageA_async(aA[0], gs[0].A, gs[0].ld, m0, mmax, gs[0].koff, tid);
    CPCOMMIT();
    for (int g = 0; g < ng; g++) {
        if (g + 1 < ng) {
            stageA_async(aA[(g + 1) & 1], gs[g + 1].A, gs[g + 1].ld, m0, mmax,
                         gs[g + 1].koff, tid);
            CPCOMMIT(); CPWAIT1();
        } else CPWAIT0();
        __syncthreads();
        int nb = gs[g].B1 ? 2 : 1;
        for (int j = 0; j < nb; j++) {
            const __nv_bfloat16* Bg = (j == 0) ? gs[g].B0 : gs[g].B1;
            stageB_sync(smBp, Bg + (size_t)n0 * gs[g].ld, gs[g].ld, gs[g].koff, tid);
            __syncthreads();
            mma_pass64(aA[g & 1], smem_u32(smBp), 0, warp_m, warp_n, lane, acc);
            __syncthreads();
        }
    }
}

// ---------------- fuse1x1: acc = x_ac @ Wx (3-term); out = relu_conv2 + acc + b1x1 ----------------
__global__ __launch_bounds__(256)
void fuse1x1_kernel(const float* __restrict__ bx)
{
    __shared__ __align__(128) __nv_bfloat16 smA[2][128 * 64];
    __shared__ __align__(128) __nv_bfloat16 smB[128 * 64];

    const int tid = threadIdx.x, lane = tid & 31, wid = tid >> 5;
    const int warp_m = wid & 3, warp_n = wid >> 2;
    const int m0 = blockIdx.x * 128;

    float acc[2][8][4] = {};
    FcGroup gs[2] = {
        {g_xah, g_wxh, g_wxl, 64, 0},
        {g_xal, g_wxh, nullptr, 64, 0},
    };
    fc_run(gs, 2, m0, NPIX, 0, smem_u32(smA[0]), smem_u32(smA[1]), (char*)smB,
           tid, warp_m, warp_n, lane, acc);

    const uint32_t* c2h = (const uint32_t*)g_c2h;
    const uint32_t* c2l = (const uint32_t*)g_c2l;
    const int g = lane >> 2, t4 = lane & 3;
    #pragma unroll
    for (int i = 0; i < 2; i++) {
        size_t pA = (size_t)m0 + warp_m * 32 + i * 16 + g;
        size_t pB = pA + 8;
        #pragma unroll
        for (int j = 0; j < 8; j++) {
            int col = warp_n * 64 + j * 8 + t4 * 2;
            float bb0 = bx[col], bb1 = bx[col + 1];
            uint32_t ph = c2h[pA * 64 + (col >> 1)], pl = c2l[pA * 64 + (col >> 1)];
            float f0 = bf2f_lo(ph) + bf2f_lo(pl);
            float f1 = bf2f_hi(ph) + bf2f_hi(pl);
            *(float2*)&g_xat[pA * 128 + col] =
                make_float2(acc[i][j][0] + bb0 + f0, acc[i][j][1] + bb1 + f1);
            uint32_t qh = c2h[pB * 64 + (col >> 1)], ql = c2l[pB * 64 + (col >> 1)];
            float f2 = bf2f_lo(qh) + bf2f_lo(ql);
            float f3 = bf2f_hi(qh) + bf2f_hi(ql);
            *(float2*)&g_xat[pB * 128 + col] =
                make_float2(acc[i][j][2] + bb0 + f2, acc[i][j][3] + bb1 + f3);
        }
    }
}

// ---------------- g_xat -> x_after NCHW fp32 ----------------
__global__ void xat2nchw_kernel(float* __restrict__ dst)
{
    __shared__ float s[32 * 33];
    int tid = threadIdx.x;
    int x0 = blockIdx.x * 32, y = blockIdx.y;
    int b = blockIdx.z >> 2, c0 = (blockIdx.z & 3) * 32;
    #pragma unroll
    for (int i = 0; i < 4; i++) {
        int lin = tid + i * 256;
        int c = lin & 31, x = lin >> 5;
        s[x * 33 + c] = g_xat[(((size_t)b * 256 + y) * 256 + x0 + x) * 128 + c0 + c];
    }
    __syncthreads();
    #pragma unroll
    for (int i = 0; i < 4; i++) {
        int lin = tid + i * 256;
        int x = lin & 31, c = lin >> 5;
        dst[(((size_t)b * 128 + c0 + c) * 256 + y) * 256 + x0 + x] = s[x * 33 + c];
    }
}

// ---------------- bilinear sampling ----------------
__global__ void sample_kernel(const float* __restrict__ p)
{
    int gid  = blockIdx.x * blockDim.x + threadIdx.x;
    int wid  = gid >> 5;
    int lane = gid & 31;
    if (wid >= NPTS) return;
    int b = (wid >= N_) ? 1 : 0;

    float sx = p[(size_t)wid * 3 + 0];
    float sy = p[(size_t)wid * 3 + 1];
    float px = fminf(fmaxf(sx * 255.f, 0.f), 255.f);
    float py = fminf(fmaxf(sy * 255.f, 0.f), 255.f);
    float x0f = floorf(px), y0f = floorf(py);
    int x0 = (int)x0f, y0 = (int)y0f;
    int x1 = min(x0 + 1, 255), y1 = min(y0 + 1, 255);
    float wx = px - x0f, wy = py - y0f;
    float w00 = (1.f - wx) * (1.f - wy);
    float w01 = wx * (1.f - wy);
    float w10 = (1.f - wx) * wy;
    float w11 = wx * wy;

    const float4* F = (const float4*)g_xat;
    size_t r00 = ((size_t)(b * 256 + y0) * 256 + x0) * 32 + lane;
    size_t r01 = ((size_t)(b * 256 + y0) * 256 + x1) * 32 + lane;
    size_t r10 = ((size_t)(b * 256 + y1) * 256 + x0) * 32 + lane;
    size_t r11 = ((size_t)(b * 256 + y1) * 256 + x1) * 32 + lane;
    float4 f00 = F[r00], f01 = F[r01], f10 = F[r10], f11 = F[r11];
    float4 r;
    r.x = f00.x * w00 + f01.x * w01 + f10.x * w10 + f11.x * w11;
    r.y = f00.y * w00 + f01.y * w01 + f10.y * w10 + f11.y * w11;
    r.z = f00.z * w00 + f01.z * w01 + f10.z * w10 + f11.z * w11;
    r.w = f00.w * w00 + f01.w * w01 + f10.w * w10 + f11.w * w11;

    uint32_t h0, l0, h1, l1;
    split2(r.x, r.y, h0, l0);
    split2(r.z, r.w, h1, l1);
    uint32_t* ch = (uint32_t*)g_c0h;
    uint32_t* cl = (uint32_t*)g_c0l;
    size_t base = (size_t)wid * 64 + lane * 2;
    ch[base] = h0; ch[base + 1] = h1;
    cl[base] = l0; cl[base + 1] = l1;

    if (lane == 0) {
        int ix = min(max((int)(sx * 256.f), 0), 255);
        int iy = min(max((int)(sy * 256.f), 0), 255);
        int idx = ix + (iy << 8);
        g_idx[wid] = idx;
        atomicAdd(&g_cnt[b * RES2 + idx], 1.f);
    }
}

// ---------------- fc1: t = relu(c0 @ W1 + b1) ----------------
__global__ __launch_bounds__(256)
void fc1_hmma_kernel(const float* __restrict__ bias)
{
    __shared__ __align__(128) __nv_bfloat16 smA[2][128 * 64];
    __shared__ __align__(128) __nv_bfloat16 smB[128 * 64];

    const int tid = threadIdx.x, lane = tid & 31, wid = tid >> 5;
    const int warp_m = wid & 3, warp_n = wid >> 2;
    const int m0 = blockIdx.x * 128, n0 = blockIdx.y * 128;

    float acc[2][8][4] = {};
    FcGroup gs[4] = {
        {g_c0h, g_w1t_h, g_w1t_l, 128, 0},
        {g_c0h, g_w1t_h, g_w1t_l, 128, 64},
        {g_c0l, g_w1t_h, nullptr, 128, 0},
        {g_c0l, g_w1t_h, nullptr, 128, 64},
    };
    fc_run(gs, 4, m0, NPTS, n0, smem_u32(smA[0]), smem_u32(smA[1]), (char*)smB,
           tid, warp_m, warp_n, lane, acc);

    uint32_t* th = (uint32_t*)g_th;
    uint32_t* tl = (uint32_t*)g_tl;
    const int g = lane >> 2, t4 = lane & 3;
    #pragma unroll
    for (int i = 0; i < 2; i++) {
        int rowA = m0 + warp_m * 32 + i * 16 + g;
        int rowB = rowA + 8;
        #pragma unroll
        for (int j = 0; j < 8; j++) {
            int col = n0 + warp_n * 64 + j * 8 + t4 * 2;
            float b0 = bias[col], b1 = bias[col + 1];
            if (rowA < NPTS) {
                float v0 = fmaxf(acc[i][j][0] + b0, 0.f);
                float v1 = fmaxf(acc[i][j][1] + b1, 0.f);
                uint32_t uh, ul; split2(v0, v1, uh, ul);
                size_t o = (size_t)rowA * 128 + (col >> 1);
                th[o] = uh; tl[o] = ul;
            }
            if (rowB < NPTS) {
                float v2 = fmaxf(acc[i][j][2] + b0, 0.f);
                float v3 = fmaxf(acc[i][j][3] + b1, 0.f);
                uint32_t uh, ul; split2(v2, v3, uh, ul);
                size_t o = (size_t)rowB * 128 + (col >> 1);
                th[o] = uh; tl[o] = ul;
            }
        }
    }
}

// ---------------- fc2: c = t@W2 + b2 + c_last@Wc + bc; write c; scatter-add ----------------
__global__ __launch_bounds__(256)
void fc2_hmma_kernel(const float* __restrict__ b2, const float* __restrict__ bc,
                     float* __restrict__ outc)
{
    __shared__ __align__(128) __nv_bfloat16 smA[2][128 * 64];
    __shared__ __align__(128) __nv_bfloat16 smB[128 * 64];

    const int tid = threadIdx.x, lane = tid & 31, wid = tid >> 5;
    const int warp_m = wid & 3, warp_n = wid >> 2;
    const int m0 = blockIdx.x * 128;

    float acc[2][8][4] = {};
    FcGroup gs[10] = {
        {g_th, g_w2t_h, g_w2t_l, 256, 0},
        {g_th, g_w2t_h, g_w2t_l, 256, 64},
        {g_th, g_w2t_h, g_w2t_l, 256, 128},
        {g_th, g_w2t_h, g_w2t_l, 256, 192},
        {g_tl, g_w2t_h, nullptr, 256, 0},
        {g_tl, g_w2t_h, nullptr, 256, 64},
        {g_tl, g_w2t_h, nullptr, 256, 128},
        {g_tl, g_w2t_h, nullptr, 256, 192},
        {g_clh, g_wct_h, g_wct_l, 64, 0},
        {g_cll, g_wct_h, nullptr, 64, 0},
    };
    fc_run(gs, 10, m0, NPTS, 0, smem_u32(smA[0]), smem_u32(smA[1]), (char*)smB,
           tid, warp_m, warp_n, lane, acc);

    const int g = lane >> 2, t4 = lane & 3;
    int rows[4], idxs[4], bbs[4];
    #pragma unroll
    for (int i = 0; i < 2; i++) {
        rows[i * 2]     = m0 + warp_m * 32 + i * 16 + g;
        rows[i * 2 + 1] = rows[i * 2] + 8;
    }
    #pragma unroll
    for (int k = 0; k < 4; k++) {
        idxs[k] = 0; bbs[k] = 0;
        if (rows[k] < NPTS) { idxs[k] = g_idx[rows[k]]; bbs[k] = (rows[k] >= N_) ? 1 : 0; }
    }
    #pragma unroll
    for (int i = 0; i < 2; i++) {
        #pragma unroll
        for (int j = 0; j < 8; j++) {
            int col = warp_n * 64 + j * 8 + t4 * 2;
            float bb0 = b2[col] + bc[col], bb1 = b2[col + 1] + bc[col + 1];
            int rA = rows[i * 2], rB = rows[i * 2 + 1];
            float v0 = acc[i][j][0] + bb0, v1 = acc[i][j][1] + bb1;
            float v2 = acc[i][j][2] + bb0, v3 = acc[i][j][3] + bb1;
            if (rA < NPTS) {
                *(float2*)(outc + (size_t)rA * 128 + col) = make_float2(v0, v1);
                int ia = idxs[i * 2], ba = bbs[i * 2];
                atomicAdd(&g_sums[((size_t)(ba * 128 + col)) * RES2 + ia], v0);
                atomicAdd(&g_sums[((size_t)(ba * 128 + col + 1)) * RES2 + ia], v1);
            }
            if (rB < NPTS) {
                *(float2*)(outc + (size_t)rB * 128 + col) = make_float2(v2, v3);
                int ib = idxs[i * 2 + 1], bbx = bbs[i * 2 + 1];
                atomicAdd(&g_sums[((size_t)(bbx * 128 + col)) * RES2 + ib], v2);
                atomicAdd(&g_sums[((size_t)(bbx * 128 + col + 1)) * RES2 + ib], v3);
            }
        }
    }
}

// ---------------- plane finalize + maxpool ----------------
__global__ void plane_kernel(float* __restrict__ dout)
{
    int i = blockIdx.x * blockDim.x + threadIdx.x;
    if (i >= B_ * 128 * RES2) return;
    int b = i >> 23;
    int idx = i & 65535;
    float cnt = g_cnt[(b << 16) + idx];
    dout[BP_OFF + i] = g_sums[i] / fmaxf(cnt, 1.f);
}

__global__ void pool_kernel(float* __restrict__ dout)
{
    int i = blockIdx.x * blockDim.x + threadIdx.x;
    if (i >= B_ * 128 * 128 * 128) return;
    int px = i & 127, py = (i >> 7) & 127, bc = i >> 14;
    const float* pl = dout + BP_OFF + (size_t)bc * RES2;
    int r0 = (py * 2) * 256 + px * 2;
    float v = fmaxf(fmaxf(pl[r0], pl[r0 + 1]), fmaxf(pl[r0 + 256], pl[r0 + 257]));
    dout[OUT_OFF + i] = v;
}

// ---------------- launch ----------------
extern "C" void kernel_launch(void* const* d_in, const int* in_sizes, int n_in,
                              void* d_out, int out_size)
{
    const float* p     = (const float*)d_in[0];
    const float* x_xy  = (const float*)d_in[1];
    const float* x_ac  = (const float*)d_in[2];
    const float* clast = (const float*)d_in[3];
    const float* w1    = (const float*)d_in[4];
    const float* bb1   = (const float*)d_in[5];
    const float* w2    = (const float*)d_in[6];
    const float* bb2   = (const float*)d_in[7];
    const float* w1x1  = (const float*)d_in[8];
    const float* b1x1  = (const float*)d_in[9];
    const float* wfc1  = (const float*)d_in[10];
    const float* bfc1  = (const float*)d_in[11];
    const float* wfc2  = (const float*)d_in[12];
    const float* bfc2  = (const float*)d_in[13];
    const float* wfcc  = (const float*)d_in[14];
    const float* bfcc  = (const float*)d_in[15];
    float* out = (float*)d_out;

    zero_kernel<<<2048, 256>>>();
    wconv_kernel<<<576, 256>>>(wfc1, wfc2, wfcc, w1, w2, w1x1);
    clconv_kernel<<<(NPTS * 32 + 255) / 256, 256>>>(clast);
    cvt_kernel<<<dim3(4, 256, 2), 256>>>(x_xy, 0);
    cvt_kernel<<<dim3(4, 256, 2), 256>>>(x_ac, 1);
    conv_hmma_kernel<64, 1><<<dim3(2, 256, 4), 256>>>(bb1);
    conv_hmma_kernel<128, 2><<<dim3(2, 256, 4), 256>>>(bb2);
    fuse1x1_kernel<<<NPIX / 128, 256>>>(b1x1);
    xat2nchw_kernel<<<dim3(8, 256, 8), 256>>>(out + XA_OFF);
    sample_kernel<<<(NPTS * 32 + 255) / 256, 256>>>(p);
    fc1_hmma_kernel<<<dim3(MTILES, 2), 256>>>(bfc1);
    fc2_hmma_kernel<<<dim3(MTILES, 1), 256>>>(bfc2, bfcc, out + C_OFF);
    plane_kernel<<<(B_ * 128 * RES2) / 256, 256>>>(out);
    pool_kernel<<<(B_ * 128 * 128 * 128) / 256, 256>>>(out);
}